// round 10
// baseline (speedup 1.0000x reference)
#include <cuda_runtime.h>
#include <cuda_bf16.h>
#include <math.h>
#include <cstdint>

#define BB 32
#define DD 512
#define TT 64
#define RR 49
#define TR 3136
#define KK 64
#define OUTN 1024
#define KD 32768

// ================= mma / ldmatrix =================
__device__ __forceinline__ void mma_bf16(float* c, const uint32_t* a, const uint32_t* b) {
    asm volatile(
        "mma.sync.aligned.m16n8k16.row.col.f32.bf16.bf16.f32 "
        "{%0,%1,%2,%3}, {%4,%5,%6,%7}, {%8,%9}, {%0,%1,%2,%3};"
        : "+f"(c[0]), "+f"(c[1]), "+f"(c[2]), "+f"(c[3])
        : "r"(a[0]), "r"(a[1]), "r"(a[2]), "r"(a[3]), "r"(b[0]), "r"(b[1]));
}
__device__ __forceinline__ void ldmx4(uint32_t* r, uint32_t a) {
    asm volatile("ldmatrix.sync.aligned.m8n8.x4.shared.b16 {%0,%1,%2,%3}, [%4];"
                 : "=r"(r[0]), "=r"(r[1]), "=r"(r[2]), "=r"(r[3]) : "r"(a));
}
__device__ __forceinline__ void ldmx4t(uint32_t* r, uint32_t a) {
    asm volatile("ldmatrix.sync.aligned.m8n8.x4.trans.shared.b16 {%0,%1,%2,%3}, [%4];"
                 : "=r"(r[0]), "=r"(r[1]), "=r"(r[2]), "=r"(r[3]) : "r"(a));
}
__device__ __forceinline__ void ldmx2(uint32_t* r, uint32_t a) {
    asm volatile("ldmatrix.sync.aligned.m8n8.x2.shared.b16 {%0,%1}, [%2];"
                 : "=r"(r[0]), "=r"(r[1]) : "r"(a));
}
__device__ __forceinline__ uint32_t smem_u32(const void* p) {
    uint32_t a;
    asm("{ .reg .u64 t; cvta.to.shared.u64 t, %1; cvt.u32.u64 %0, t; }" : "=r"(a) : "l"(p));
    return a;
}
__device__ __forceinline__ void split_bf(float f, __nv_bfloat16& h, __nv_bfloat16& l) {
    h = __float2bfloat16(f);
    l = __float2bfloat16(f - __bfloat162float(h));
}
__device__ __forceinline__ uint32_t pkbf(__nv_bfloat16 a, __nv_bfloat16 b) {
    return (uint32_t)__bfloat16_as_ushort(a) | ((uint32_t)__bfloat16_as_ushort(b) << 16);
}
__device__ __forceinline__ void split4(float4 v, uint2& vh, uint2& vl) {
    __nv_bfloat16 h0, l0, h1, l1, h2, l2, h3, l3;
    split_bf(v.x, h0, l0); split_bf(v.y, h1, l1);
    split_bf(v.z, h2, l2); split_bf(v.w, h3, l3);
    vh = make_uint2(pkbf(h0, h1), pkbf(h2, h3));
    vl = make_uint2(pkbf(l0, l1), pkbf(l2, l3));
}

// ================= scratch =================
__device__ __align__(256) __nv_bfloat16 g_ass_hi[(size_t)BB * KK * TR];
__device__ __align__(256) __nv_bfloat16 g_ass_lo[(size_t)BB * KK * TR];
__device__ __align__(256) float g_asum[BB * KK];
__device__ __align__(256) float g_vlad[BB * KD];
__device__ __align__(256) float g_bsq[BB];
__device__ __align__(256) float g_outpre[BB * OUTN];

__global__ void k_zero() {
    int i = blockIdx.x * 256 + threadIdx.x;
    g_vlad[i] = 0.f;
    if (i < BB * OUTN) g_outpre[i] = 0.f;
    if (i < BB * KK)   g_asum[i]   = 0.f;
    if (i < BB)        g_bsq[i]    = 0.f;
}

extern __shared__ unsigned char smx[];

// ================= GEMM1: logits -> softmax -> assign + a_sum =================
// grid (32, 25), block 256. Ping-pong smem: store chunk q+1 while MMAing chunk q.
#define X1ROW 136
#define W1ROW 72
#define G1_XH 0
#define G1_XL (64 * X1ROW)
#define G1_WH (2 * 64 * X1ROW)
#define G1_WL (2 * 64 * X1ROW + 64 * W1ROW)
#define G1_END (2 * 64 * X1ROW + 2 * 64 * W1ROW)
#define G1_SMEM (2 * G1_END * 2 + 256)

__device__ __forceinline__ void g1_store(uint16_t* S, int buf, const float4* rx, const float4* rw,
                                         const int* xrow, int xc4, int tid) {
    uint16_t* B = S + buf * G1_END;
#pragma unroll
    for (int j = 0; j < 8; j++) {
        uint2 vh, vl; split4(rx[j], vh, vl);
        *(uint2*)(B + G1_XH + xrow[j] * X1ROW + xc4 * 4) = vh;
        *(uint2*)(B + G1_XL + xrow[j] * X1ROW + xc4 * 4) = vl;
    }
    const int wrow = tid >> 4, wc4 = tid & 15;
#pragma unroll
    for (int j = 0; j < 4; j++) {
        uint2 vh, vl; split4(rw[j], vh, vl);
        *(uint2*)(B + G1_WH + (wrow + j * 16) * W1ROW + wc4 * 4) = vh;
        *(uint2*)(B + G1_WL + (wrow + j * 16) * W1ROW + wc4 * 4) = vl;
    }
}

__global__ __launch_bounds__(256) void k_g1(const float* __restrict__ x,
                                            const int* __restrict__ mask,
                                            const float* __restrict__ conv_w) {
    uint16_t* S = (uint16_t*)smx;
    float* sAs = (float*)(S + 2 * G1_END);
    const uint32_t sb = smem_u32(S);
    const int tid = threadIdx.x, wid = tid >> 5, lane = tid & 31;
    const int g = lane >> 2, t = lane & 3;
    const int b = blockIdx.x, tr0 = blockIdx.y * 128;

    if (tid < 64) sAs[tid] = 0.f;

    float cacc[8][4];
#pragma unroll
    for (int n = 0; n < 8; n++)
#pragma unroll
        for (int i = 0; i < 4; i++) cacc[n][i] = 0.f;

    const uint32_t aoff = (uint32_t)(((lane >> 4) * 8 + (lane & 7)) * X1ROW +
                                     wid * 16 + ((lane >> 3) & 1) * 8) * 2;
    const int L = lane & 15;
    const uint32_t boff = (uint32_t)((L & 7) * W1ROW + (L >> 3) * 8) * 2;

    const int xrow[8] = { tid >> 5, (tid + 256) >> 5, (tid + 512) >> 5, (tid + 768) >> 5,
                          (tid + 1024) >> 5, (tid + 1280) >> 5, (tid + 1536) >> 5, (tid + 1792) >> 5 };
    const int xc4 = tid & 31;
    const int xtr = tr0 + xc4 * 4;
    const bool xok = (xtr < TR);
    const int wrow = tid >> 4, wc4 = tid & 15;

    float4 rx[8], rw[4];
    // load q=0, store to buf0
#pragma unroll
    for (int j = 0; j < 8; j++)
        rx[j] = xok ? *(const float4*)(x + ((size_t)b * DD + xrow[j]) * TR + xtr)
                    : make_float4(0.f, 0.f, 0.f, 0.f);
#pragma unroll
    for (int j = 0; j < 4; j++)
        rw[j] = *(const float4*)(conv_w + (wrow + j * 16) * DD + wc4 * 4);
    g1_store(S, 0, rx, rw, xrow, xc4, tid);
    __syncthreads();
    // load q=1
#pragma unroll
    for (int j = 0; j < 8; j++)
        rx[j] = xok ? *(const float4*)(x + ((size_t)b * DD + 64 + xrow[j]) * TR + xtr)
                    : make_float4(0.f, 0.f, 0.f, 0.f);
#pragma unroll
    for (int j = 0; j < 4; j++)
        rw[j] = *(const float4*)(conv_w + (wrow + j * 16) * DD + 64 + wc4 * 4);

    for (int q = 0; q < 8; q++) {
        if (q + 1 < 8) g1_store(S, (q + 1) & 1, rx, rw, xrow, xc4, tid);
        if (q + 2 < 8) {
            const int dq = (q + 2) * 64;
#pragma unroll
            for (int j = 0; j < 8; j++)
                rx[j] = xok ? *(const float4*)(x + ((size_t)b * DD + dq + xrow[j]) * TR + xtr)
                            : make_float4(0.f, 0.f, 0.f, 0.f);
#pragma unroll
            for (int j = 0; j < 4; j++)
                rw[j] = *(const float4*)(conv_w + (wrow + j * 16) * DD + dq + wc4 * 4);
        }
        const uint32_t bufb = sb + (uint32_t)((q & 1) * G1_END) * 2;
#pragma unroll
        for (int s = 0; s < 4; s++) {
            uint32_t ah[4], al[4];
            ldmx4t(ah, bufb + G1_XH * 2 + (uint32_t)(s * 16 * X1ROW) * 2 + aoff);
            ldmx4t(al, bufb + G1_XL * 2 + (uint32_t)(s * 16 * X1ROW) * 2 + aoff);
#pragma unroll
            for (int n = 0; n < 8; n++) {
                uint32_t bh[2], bl[2];
                uint32_t bb = (uint32_t)(n * 8 * W1ROW + s * 16) * 2 + boff;
                ldmx2(bh, bufb + G1_WH * 2 + bb);
                ldmx2(bl, bufb + G1_WL * 2 + bb);
                mma_bf16(cacc[n], ah, bh);
                mma_bf16(cacc[n], ah, bl);
                mma_bf16(cacc[n], al, bh);
            }
        }
        __syncthreads();
    }

    const int tra = tr0 + wid * 16 + g;
    const int trb = tra + 8;
    float ma = -1e30f, mb = -1e30f;
#pragma unroll
    for (int n = 0; n < 8; n++) {
        ma = fmaxf(ma, fmaxf(cacc[n][0], cacc[n][1]));
        mb = fmaxf(mb, fmaxf(cacc[n][2], cacc[n][3]));
    }
    ma = fmaxf(ma, __shfl_xor_sync(0xffffffffu, ma, 1));
    ma = fmaxf(ma, __shfl_xor_sync(0xffffffffu, ma, 2));
    mb = fmaxf(mb, __shfl_xor_sync(0xffffffffu, mb, 1));
    mb = fmaxf(mb, __shfl_xor_sync(0xffffffffu, mb, 2));
    float sa = 0.f, sb2 = 0.f;
#pragma unroll
    for (int n = 0; n < 8; n++) {
        cacc[n][0] = __expf(cacc[n][0] - ma); sa += cacc[n][0];
        cacc[n][1] = __expf(cacc[n][1] - ma); sa += cacc[n][1];
        cacc[n][2] = __expf(cacc[n][2] - mb); sb2 += cacc[n][2];
        cacc[n][3] = __expf(cacc[n][3] - mb); sb2 += cacc[n][3];
    }
    sa  += __shfl_xor_sync(0xffffffffu, sa, 1);
    sa  += __shfl_xor_sync(0xffffffffu, sa, 2);
    sb2 += __shfl_xor_sync(0xffffffffu, sb2, 1);
    sb2 += __shfl_xor_sync(0xffffffffu, sb2, 2);
    const float mva = (tra < TR) ? (float)mask[b * TT + tra / RR] : 0.f;
    const float mvb = (trb < TR) ? (float)mask[b * TT + trb / RR] : 0.f;
    const float inva = mva / sa, invb = mvb / sb2;

#pragma unroll
    for (int n = 0; n < 8; n++) {
#pragma unroll
        for (int i = 0; i < 2; i++) {
            const int k = n * 8 + 2 * t + i;
            float aa = cacc[n][i] * inva;
            float ab = cacc[n][2 + i] * invb;
            if (tra < TR) {
                __nv_bfloat16 h, l; split_bf(aa, h, l);
                size_t o = ((size_t)b * KK + k) * TR + tra;
                g_ass_hi[o] = h; g_ass_lo[o] = l;
            }
            if (trb < TR) {
                __nv_bfloat16 h, l; split_bf(ab, h, l);
                size_t o = ((size_t)b * KK + k) * TR + trb;
                g_ass_hi[o] = h; g_ass_lo[o] = l;
            }
            float sum = aa + ab;
            sum += __shfl_xor_sync(0xffffffffu, sum, 4);
            sum += __shfl_xor_sync(0xffffffffu, sum, 8);
            sum += __shfl_xor_sync(0xffffffffu, sum, 16);
            if (g == 0) atomicAdd(&sAs[k], sum);
        }
    }
    __syncthreads();
    if (tid < 64) atomicAdd(&g_asum[b * 64 + tid], sAs[tid]);
}

// ================= GEMM2: vlad_partial[b,k,d] += sum_tr a*x =================
// grid (32, 4, 4), block 256. Ping-pong smem.
#define X2ROW 72
#define G2_XH 0
#define G2_XL (128 * X2ROW)
#define G2_AH (2 * 128 * X2ROW)
#define G2_AL (2 * 128 * X2ROW + 64 * X2ROW)
#define G2_END (2 * 128 * X2ROW + 2 * 64 * X2ROW)
#define G2_SMEM (2 * G2_END * 2 + 256)

__device__ __forceinline__ void g2_store(uint16_t* S, int buf, const float4* rx,
                                         const uint4* rah, const uint4* ral,
                                         int xrow_lo, int xc4, int arow_lo, int ac8) {
    uint16_t* B = S + buf * G2_END;
#pragma unroll
    for (int j = 0; j < 8; j++) {
        uint2 vh, vl; split4(rx[j], vh, vl);
        *(uint2*)(B + G2_XH + (xrow_lo + j * 16) * X2ROW + xc4 * 4) = vh;
        *(uint2*)(B + G2_XL + (xrow_lo + j * 16) * X2ROW + xc4 * 4) = vl;
    }
#pragma unroll
    for (int j = 0; j < 2; j++) {
        int row = arow_lo + j * 32;
        *(uint2*)(B + G2_AH + row * X2ROW + ac8 * 8)     = make_uint2(rah[j].x, rah[j].y);
        *(uint2*)(B + G2_AH + row * X2ROW + ac8 * 8 + 4) = make_uint2(rah[j].z, rah[j].w);
        *(uint2*)(B + G2_AL + row * X2ROW + ac8 * 8)     = make_uint2(ral[j].x, ral[j].y);
        *(uint2*)(B + G2_AL + row * X2ROW + ac8 * 8 + 4) = make_uint2(ral[j].z, ral[j].w);
    }
}

__global__ __launch_bounds__(256) void k_g2(const float* __restrict__ x) {
    uint16_t* S = (uint16_t*)smx;
    const uint32_t sbb = smem_u32(S);
    const int tid = threadIdx.x, wid = tid >> 5, lane = tid & 31;
    const int g = lane >> 2, t = lane & 3;
    const int b = blockIdx.x, d0 = blockIdx.y * 128, sp = blockIdx.z;
    const int c0 = sp ? 12 * sp + 1 : 0;
    const int c1 = (sp == 3) ? 49 : 12 * (sp + 1) + 1;

    float cacc[8][4];
#pragma unroll
    for (int n = 0; n < 8; n++)
#pragma unroll
        for (int i = 0; i < 4; i++) cacc[n][i] = 0.f;

    const uint32_t aoff = (uint32_t)((wid * 16 + (lane & 15)) * X2ROW + (lane >> 4) * 8) * 2;
    const int L = lane & 15;
    const uint32_t boff = (uint32_t)((L & 7) * X2ROW + (L >> 3) * 8) * 2;

    const int xrow_lo = tid >> 4, xc4 = tid & 15;
    const int arow_lo = tid >> 3, ac8 = tid & 7;

    float4 rx[8];
    uint4 rah[2], ral[2];

    auto loadc = [&](int c) {
        const int trn = c * 64;
#pragma unroll
        for (int j = 0; j < 8; j++)
            rx[j] = *(const float4*)(x + ((size_t)b * DD + d0 + xrow_lo + j * 16) * TR + trn + xc4 * 4);
#pragma unroll
        for (int j = 0; j < 2; j++) {
            size_t src = ((size_t)b * KK + arow_lo + j * 32) * TR + trn + ac8 * 8;
            rah[j] = *(const uint4*)(g_ass_hi + src);
            ral[j] = *(const uint4*)(g_ass_lo + src);
        }
    };

    loadc(c0);
    g2_store(S, 0, rx, rah, ral, xrow_lo, xc4, arow_lo, ac8);
    __syncthreads();
    if (c0 + 1 < c1) loadc(c0 + 1);

    for (int c = c0; c < c1; c++) {
        const int pb = (c - c0) & 1;
        if (c + 1 < c1) g2_store(S, pb ^ 1, rx, rah, ral, xrow_lo, xc4, arow_lo, ac8);
        if (c + 2 < c1) loadc(c + 2);

        const uint32_t bufb = sbb + (uint32_t)(pb * G2_END) * 2;
#pragma unroll
        for (int s = 0; s < 4; s++) {
            uint32_t ah[4], al[4];
            ldmx4(ah, bufb + G2_XH * 2 + (uint32_t)(s * 16) * 2 + aoff);
            ldmx4(al, bufb + G2_XL * 2 + (uint32_t)(s * 16) * 2 + aoff);
#pragma unroll
            for (int n = 0; n < 8; n++) {
                uint32_t bh[2], bl[2];
                uint32_t bb = (uint32_t)(n * 8 * X2ROW + s * 16) * 2 + boff;
                ldmx2(bh, bufb + G2_AH * 2 + bb);
                ldmx2(bl, bufb + G2_AL * 2 + bb);
                mma_bf16(cacc[n], ah, bh);
                mma_bf16(cacc[n], ah, bl);
                mma_bf16(cacc[n], al, bh);
            }
        }
        __syncthreads();
    }

    const int da = d0 + wid * 16 + g;
    const int db = da + 8;
#pragma unroll
    for (int n = 0; n < 8; n++) {
#pragma unroll
        for (int i = 0; i < 2; i++) {
            const int k = n * 8 + 2 * t + i;
            atomicAdd(&g_vlad[((size_t)b * KK + k) * DD + da], cacc[n][i]);
            atomicAdd(&g_vlad[((size_t)b * KK + k) * DD + db], cacc[n][2 + i]);
        }
    }
}

// ================= K3: subtract a_sum*centroid, intra-norm, per-b sumsq =================
__global__ __launch_bounds__(128) void k_intranorm(const float* __restrict__ centroids) {
    __shared__ float sred[4];
    const int row = blockIdx.x;
    const int tid = threadIdx.x, lane = tid & 31, w = tid >> 5;
    const float as = g_asum[row];
    float4* v = (float4*)(g_vlad + (size_t)row * 512);
    float4 val = v[tid];
    const float4 cv = ((const float4*)(centroids + (size_t)(row & 63) * DD))[tid];
    val.x -= as * cv.x; val.y -= as * cv.y; val.z -= as * cv.z; val.w -= as * cv.w;
    float ss = val.x * val.x + val.y * val.y + val.z * val.z + val.w * val.w;
    ss += __shfl_xor_sync(0xffffffffu, ss, 16);
    ss += __shfl_xor_sync(0xffffffffu, ss, 8);
    ss += __shfl_xor_sync(0xffffffffu, ss, 4);
    ss += __shfl_xor_sync(0xffffffffu, ss, 2);
    ss += __shfl_xor_sync(0xffffffffu, ss, 1);
    if (lane == 0) sred[w] = ss;
    __syncthreads();
    float tot = sred[0] + sred[1] + sred[2] + sred[3];
    float scale = 1.f / fmaxf(sqrtf(tot), 1e-12f);
    val.x *= scale; val.y *= scale; val.z *= scale; val.w *= scale;
    v[tid] = val;
    if (tid == 0) atomicAdd(&g_bsq[row >> 6], tot * scale * scale);
}

// ================= K4: reduction GEMM on HMMA, ping-pong dynamic smem =================
#define RROW 72
#define RD_WH 0
#define RD_WL (64 * RROW)
#define RD_VH (2 * 64 * RROW)
#define RD_VL (2 * 64 * RROW + 32 * RROW)
#define RD_END (2 * 64 * RROW + 2 * 32 * RROW)
#define RD_SMEM (2 * RD_END * 2 + 256)

__global__ __launch_bounds__(256) void k_reduce(const float* __restrict__ red_w) {
    uint16_t* S = (uint16_t*)smx;
    float* sBS = (float*)(S + 2 * RD_END);
    const uint32_t sbm = smem_u32(S);
    const int tid = threadIdx.x, wid = tid >> 5, lane = tid & 31;
    const int g = lane >> 2, t = lane & 3;
    const int o0 = blockIdx.x * 64;
    const int j0 = blockIdx.y * 2048;
    const int warp_m = (wid & 3) * 16;
    const int warp_n = (wid >> 2) * 16;

    if (tid < 32) sBS[tid] = 1.f / fmaxf(sqrtf(g_bsq[tid]), 1e-12f);
    __syncthreads();

    float cacc[2][4];
#pragma unroll
    for (int n = 0; n < 2; n++)
#pragma unroll
        for (int i = 0; i < 4; i++) cacc[n][i] = 0.f;

    const uint32_t aoff = (uint32_t)((warp_m + (lane & 15)) * RROW + (lane >> 4) * 8) * 2;
    const uint32_t boff = (uint32_t)((warp_n + (lane & 7) + ((lane >> 4) & 1) * 8) * RROW +
                                     ((lane >> 3) & 1) * 8) * 2;

    const int wrow_lo = tid >> 4, wc4 = tid & 15;

    float4 rw[4], rv[2];
    auto loadc = [&](int c) {
        const int jc = j0 + c * 64;
#pragma unroll
        for (int j = 0; j < 4; j++)
            rw[j] = *(const float4*)(red_w + (size_t)(o0 + wrow_lo + j * 16) * KD + jc + wc4 * 4);
#pragma unroll
        for (int j = 0; j < 2; j++)
            rv[j] = *(const float4*)(g_vlad + (size_t)(wrow_lo + j * 16) * KD + jc + wc4 * 4);
    };
    auto storec = [&](int buf) {
        uint16_t* B = S + buf * RD_END;
#pragma unroll
        for (int j = 0; j < 4; j++) {
            uint2 vh, vl; split4(rw[j], vh, vl);
            *(uint2*)(B + RD_WH + (wrow_lo + j * 16) * RROW + wc4 * 4) = vh;
            *(uint2*)(B + RD_WL + (wrow_lo + j * 16) * RROW + wc4 * 4) = vl;
        }
#pragma unroll
        for (int j = 0; j < 2; j++) {
            int row = wrow_lo + j * 16;
            float bs = sBS[row];
            float4 vv = rv[j];
            vv.x *= bs; vv.y *= bs; vv.z *= bs; vv.w *= bs;
            uint2 vh, vl; split4(vv, vh, vl);
            *(uint2*)(B + RD_VH + row * RROW + wc4 * 4) = vh;
            *(uint2*)(B + RD_VL + row * RROW + wc4 * 4) = vl;
        }
    };

    loadc(0);
    storec(0);
    __syncthreads();
    loadc(1);

    for (int c = 0; c < 32; c++) {
        if (c + 1 < 32) storec((c + 1) & 1);
        if (c + 2 < 32) loadc(c + 2);

        const uint32_t bufb = sbm + (uint32_t)((c & 1) * RD_END) * 2;
#pragma unroll
        for (int ks = 0; ks < 4; ks++) {
            const uint32_t co = (uint32_t)(ks * 16) * 2;
            uint32_t ah[4], al[4], bh[4], bl[4];
            ldmx4(ah, bufb + RD_WH * 2 + co + aoff);
            ldmx4(al, bufb + RD_WL * 2 + co + aoff);
            ldmx4(bh, bufb + RD_VH * 2 + co + boff);
            ldmx4(bl, bufb + RD_VL * 2 + co + boff);
            mma_bf16(cacc[0], ah, bh);     mma_bf16(cacc[0], ah, bl);
            mma_bf16(cacc[0], al, bh);
            mma_bf16(cacc[1], ah, bh + 2); mma_bf16(cacc[1], ah, bl + 2);
            mma_bf16(cacc[1], al, bh + 2);
        }
        __syncthreads();
    }

#pragma unroll
    for (int nt = 0; nt < 2; nt++) {
        const int bcol = warp_n + nt * 8 + 2 * t;
        const int oa = o0 + warp_m + g;
        atomicAdd(&g_outpre[(size_t)bcol * OUTN + oa],           cacc[nt][0]);
        atomicAdd(&g_outpre[(size_t)(bcol + 1) * OUTN + oa],     cacc[nt][1]);
        atomicAdd(&g_outpre[(size_t)bcol * OUTN + oa + 8],       cacc[nt][2]);
        atomicAdd(&g_outpre[(size_t)(bcol + 1) * OUTN + oa + 8], cacc[nt][3]);
    }
}

// ================= K5: LayerNorm =================
__global__ __launch_bounds__(256) void k_ln(
    const float* __restrict__ gamma, const float* __restrict__ beta,
    float* __restrict__ out)
{
    __shared__ float sred[8];
    const int b = blockIdx.x, tid = threadIdx.x, lane = tid & 31, w = tid >> 5;
    float4 v = ((const float4*)(g_outpre + (size_t)b * OUTN))[tid];
    float s = v.x + v.y + v.z + v.w;
    s += __shfl_xor_sync(0xffffffffu, s, 16);
    s += __shfl_xor_sync(0xffffffffu, s, 8);
    s += __shfl_xor_sync(0xffffffffu, s, 4);
    s += __shfl_xor_sync(0xffffffffu, s, 2);
    s += __shfl_xor_sync(0xffffffffu, s, 1);
    if (lane == 0) sred[w] = s;
    __syncthreads();
    float tot = 0.f;
#pragma unroll
    for (int i = 0; i < 8; i++) tot += sred[i];
    const float mu = tot * (1.f / 1024.f);
    float dx0 = v.x - mu, dx1 = v.y - mu, dx2 = v.z - mu, dx3 = v.w - mu;
    float vs = dx0 * dx0 + dx1 * dx1 + dx2 * dx2 + dx3 * dx3;
    vs += __shfl_xor_sync(0xffffffffu, vs, 16);
    vs += __shfl_xor_sync(0xffffffffu, vs, 8);
    vs += __shfl_xor_sync(0xffffffffu, vs, 4);
    vs += __shfl_xor_sync(0xffffffffu, vs, 2);
    vs += __shfl_xor_sync(0xffffffffu, vs, 1);
    __syncthreads();
    if (lane == 0) sred[w] = vs;
    __syncthreads();
    float vtot = 0.f;
#pragma unroll
    for (int i = 0; i < 8; i++) vtot += sred[i];
    const float inv = 1.f / sqrtf(vtot * (1.f / 1024.f) + 1e-5f);
    float4 gm = ((const float4*)gamma)[tid];
    float4 be = ((const float4*)beta)[tid];
    float4 r;
    r.x = dx0 * inv * gm.x + be.x;
    r.y = dx1 * inv * gm.y + be.y;
    r.z = dx2 * inv * gm.z + be.z;
    r.w = dx3 * inv * gm.w + be.w;
    ((float4*)(out + (size_t)b * OUTN))[tid] = r;
}

// ================= launch =================
extern "C" void kernel_launch(void* const* d_in, const int* in_sizes, int n_in,
                              void* d_out, int out_size)
{
    const float* x         = (const float*)d_in[0];
    const int*   mask      = (const int*)d_in[1];
    const float* centroids = (const float*)d_in[2];
    const float* conv_w    = (const float*)d_in[3];
    const float* red_w     = (const float*)d_in[4];
    const float* gamma     = (const float*)d_in[5];
    const float* beta      = (const float*)d_in[6];
    float* out = (float*)d_out;

    cudaFuncSetAttribute(k_g1, cudaFuncAttributeMaxDynamicSharedMemorySize, G1_SMEM);
    cudaFuncSetAttribute(k_g2, cudaFuncAttributeMaxDynamicSharedMemorySize, G2_SMEM);
    cudaFuncSetAttribute(k_reduce, cudaFuncAttributeMaxDynamicSharedMemorySize, RD_SMEM);

    k_zero<<<BB * KD / 256, 256>>>();
    k_g1<<<dim3(BB, 25), 256, G1_SMEM>>>(x, mask, conv_w);
    k_g2<<<dim3(BB, 4, 4), 256, G2_SMEM>>>(x);
    k_intranorm<<<BB * KK, 128>>>(centroids);
    k_reduce<<<dim3(16, 16), 256, RD_SMEM>>>(red_w);
    k_ln<<<BB, 256>>>(gamma, beta, out);
}

// round 11
// speedup vs baseline: 1.0009x; 1.0009x over previous
#include <cuda_runtime.h>
#include <cuda_bf16.h>
#include <math.h>
#include <cstdint>

#define BB 32
#define DD 512
#define TT 64
#define RR 49
#define TR 3136
#define KK 64
#define OUTN 1024
#define KD 32768

// ================= mma / ldmatrix =================
__device__ __forceinline__ void mma_bf16(float* c, const uint32_t* a, const uint32_t* b) {
    asm volatile(
        "mma.sync.aligned.m16n8k16.row.col.f32.bf16.bf16.f32 "
        "{%0,%1,%2,%3}, {%4,%5,%6,%7}, {%8,%9}, {%0,%1,%2,%3};"
        : "+f"(c[0]), "+f"(c[1]), "+f"(c[2]), "+f"(c[3])
        : "r"(a[0]), "r"(a[1]), "r"(a[2]), "r"(a[3]), "r"(b[0]), "r"(b[1]));
}
__device__ __forceinline__ void ldmx4(uint32_t* r, uint32_t a) {
    asm volatile("ldmatrix.sync.aligned.m8n8.x4.shared.b16 {%0,%1,%2,%3}, [%4];"
                 : "=r"(r[0]), "=r"(r[1]), "=r"(r[2]), "=r"(r[3]) : "r"(a));
}
__device__ __forceinline__ void ldmx4t(uint32_t* r, uint32_t a) {
    asm volatile("ldmatrix.sync.aligned.m8n8.x4.trans.shared.b16 {%0,%1,%2,%3}, [%4];"
                 : "=r"(r[0]), "=r"(r[1]), "=r"(r[2]), "=r"(r[3]) : "r"(a));
}
__device__ __forceinline__ void ldmx2(uint32_t* r, uint32_t a) {
    asm volatile("ldmatrix.sync.aligned.m8n8.x2.shared.b16 {%0,%1}, [%2];"
                 : "=r"(r[0]), "=r"(r[1]) : "r"(a));
}
__device__ __forceinline__ uint32_t smem_u32(const void* p) {
    uint32_t a;
    asm("{ .reg .u64 t; cvta.to.shared.u64 t, %1; cvt.u32.u64 %0, t; }" : "=r"(a) : "l"(p));
    return a;
}
__device__ __forceinline__ void split_bf(float f, __nv_bfloat16& h, __nv_bfloat16& l) {
    h = __float2bfloat16(f);
    l = __float2bfloat16(f - __bfloat162float(h));
}
__device__ __forceinline__ uint32_t pkbf(__nv_bfloat16 a, __nv_bfloat16 b) {
    return (uint32_t)__bfloat16_as_ushort(a) | ((uint32_t)__bfloat16_as_ushort(b) << 16);
}
__device__ __forceinline__ void split4(float4 v, uint2& vh, uint2& vl) {
    __nv_bfloat16 h0, l0, h1, l1, h2, l2, h3, l3;
    split_bf(v.x, h0, l0); split_bf(v.y, h1, l1);
    split_bf(v.z, h2, l2); split_bf(v.w, h3, l3);
    vh = make_uint2(pkbf(h0, h1), pkbf(h2, h3));
    vl = make_uint2(pkbf(l0, l1), pkbf(l2, l3));
}

// ================= scratch =================
__device__ __align__(256) __nv_bfloat16 g_ass_hi[(size_t)BB * KK * TR];
__device__ __align__(256) __nv_bfloat16 g_ass_lo[(size_t)BB * KK * TR];
__device__ __align__(256) float g_asum[BB * KK];
__device__ __align__(256) float g_vlad[BB * KD];
__device__ __align__(256) float g_bsq[BB];
__device__ __align__(256) float g_outpre[BB * OUTN];

__global__ void k_zero() {
    int i = blockIdx.x * 256 + threadIdx.x;
    g_vlad[i] = 0.f;
    if (i < BB * OUTN) g_outpre[i] = 0.f;
    if (i < BB * KK)   g_asum[i]   = 0.f;
    if (i < BB)        g_bsq[i]    = 0.f;
}

extern __shared__ unsigned char smx[];

// ================= GEMM1: logits -> softmax -> assign + a_sum =================
// grid (32, 25), block 256 (8 warps). Register prefetch one chunk ahead; single smem buffer.
#define X1ROW 136
#define W1ROW 72
#define G1_XH 0
#define G1_XL (64 * X1ROW)
#define G1_WH (2 * 64 * X1ROW)
#define G1_WL (2 * 64 * X1ROW + 64 * W1ROW)
#define G1_END (2 * 64 * X1ROW + 2 * 64 * W1ROW)
#define G1_SMEM (G1_END * 2 + 256)

__global__ __launch_bounds__(256) void k_g1(const float* __restrict__ x,
                                            const int* __restrict__ mask,
                                            const float* __restrict__ conv_w) {
    uint16_t* S = (uint16_t*)smx;
    float* sAs = (float*)(S + G1_END);
    const uint32_t sb = smem_u32(S);
    const int tid = threadIdx.x, wid = tid >> 5, lane = tid & 31;
    const int g = lane >> 2, t = lane & 3;
    const int b = blockIdx.x, tr0 = blockIdx.y * 128;

    if (tid < 64) sAs[tid] = 0.f;

    float cacc[8][4];
#pragma unroll
    for (int n = 0; n < 8; n++)
#pragma unroll
        for (int i = 0; i < 4; i++) cacc[n][i] = 0.f;

    const uint32_t aoff = (uint32_t)(((lane >> 4) * 8 + (lane & 7)) * X1ROW +
                                     wid * 16 + ((lane >> 3) & 1) * 8) * 2;
    const int L = lane & 15;
    const uint32_t boff = (uint32_t)((L & 7) * W1ROW + (L >> 3) * 8) * 2;

    const int xrow[8] = { tid >> 5, (tid + 256) >> 5, (tid + 512) >> 5, (tid + 768) >> 5,
                          (tid + 1024) >> 5, (tid + 1280) >> 5, (tid + 1536) >> 5, (tid + 1792) >> 5 };
    const int xc4 = tid & 31;
    const int xtr = tr0 + xc4 * 4;
    const bool xok = (xtr < TR);

    float4 rx[8];
#pragma unroll
    for (int j = 0; j < 8; j++)
        rx[j] = xok ? *(const float4*)(x + ((size_t)b * DD + xrow[j]) * TR + xtr)
                    : make_float4(0.f, 0.f, 0.f, 0.f);

    for (int q = 0; q < 8; q++) {
        __syncthreads();
#pragma unroll
        for (int j = 0; j < 8; j++) {
            uint2 vh, vl; split4(rx[j], vh, vl);
            *(uint2*)(S + G1_XH + xrow[j] * X1ROW + xc4 * 4) = vh;
            *(uint2*)(S + G1_XL + xrow[j] * X1ROW + xc4 * 4) = vl;
        }
        for (int u = tid; u < 1024; u += 256) {          // W chunk (L2-hot)
            int row = u >> 4, c4 = u & 15;
            float4 wv = *(const float4*)(conv_w + row * DD + q * 64 + c4 * 4);
            uint2 vh, vl; split4(wv, vh, vl);
            *(uint2*)(S + G1_WH + row * W1ROW + c4 * 4) = vh;
            *(uint2*)(S + G1_WL + row * W1ROW + c4 * 4) = vl;
        }
        __syncthreads();

        if (q < 7) {                                     // prefetch next chunk
#pragma unroll
            for (int j = 0; j < 8; j++)
                rx[j] = xok ? *(const float4*)(x + ((size_t)b * DD + (q + 1) * 64 + xrow[j]) * TR + xtr)
                            : make_float4(0.f, 0.f, 0.f, 0.f);
        }

#pragma unroll
        for (int s = 0; s < 4; s++) {
            uint32_t ah[4], al[4];
            ldmx4t(ah, sb + G1_XH * 2 + (uint32_t)(s * 16 * X1ROW) * 2 + aoff);
            ldmx4t(al, sb + G1_XL * 2 + (uint32_t)(s * 16 * X1ROW) * 2 + aoff);
#pragma unroll
            for (int n = 0; n < 8; n++) {
                uint32_t bh[2], bl[2];
                uint32_t bb = (uint32_t)(n * 8 * W1ROW + s * 16) * 2 + boff;
                ldmx2(bh, sb + G1_WH * 2 + bb);
                ldmx2(bl, sb + G1_WL * 2 + bb);
                mma_bf16(cacc[n], ah, bh);
                mma_bf16(cacc[n], ah, bl);
                mma_bf16(cacc[n], al, bh);
            }
        }
    }

    const int tra = tr0 + wid * 16 + g;
    const int trb = tra + 8;
    float ma = -1e30f, mb = -1e30f;
#pragma unroll
    for (int n = 0; n < 8; n++) {
        ma = fmaxf(ma, fmaxf(cacc[n][0], cacc[n][1]));
        mb = fmaxf(mb, fmaxf(cacc[n][2], cacc[n][3]));
    }
    ma = fmaxf(ma, __shfl_xor_sync(0xffffffffu, ma, 1));
    ma = fmaxf(ma, __shfl_xor_sync(0xffffffffu, ma, 2));
    mb = fmaxf(mb, __shfl_xor_sync(0xffffffffu, mb, 1));
    mb = fmaxf(mb, __shfl_xor_sync(0xffffffffu, mb, 2));
    float sa = 0.f, sb2 = 0.f;
#pragma unroll
    for (int n = 0; n < 8; n++) {
        cacc[n][0] = __expf(cacc[n][0] - ma); sa += cacc[n][0];
        cacc[n][1] = __expf(cacc[n][1] - ma); sa += cacc[n][1];
        cacc[n][2] = __expf(cacc[n][2] - mb); sb2 += cacc[n][2];
        cacc[n][3] = __expf(cacc[n][3] - mb); sb2 += cacc[n][3];
    }
    sa  += __shfl_xor_sync(0xffffffffu, sa, 1);
    sa  += __shfl_xor_sync(0xffffffffu, sa, 2);
    sb2 += __shfl_xor_sync(0xffffffffu, sb2, 1);
    sb2 += __shfl_xor_sync(0xffffffffu, sb2, 2);
    const float mva = (tra < TR) ? (float)mask[b * TT + tra / RR] : 0.f;
    const float mvb = (trb < TR) ? (float)mask[b * TT + trb / RR] : 0.f;
    const float inva = mva / sa, invb = mvb / sb2;

    // write assign first (STG latency overlaps the reduction shuffles below)
#pragma unroll
    for (int n = 0; n < 8; n++) {
#pragma unroll
        for (int i = 0; i < 2; i++) {
            const int k = n * 8 + 2 * t + i;
            float aa = cacc[n][i] * inva;
            float ab = cacc[n][2 + i] * invb;
            cacc[n][i] = aa; cacc[n][2 + i] = ab;
            if (tra < TR) {
                __nv_bfloat16 h, l; split_bf(aa, h, l);
                size_t o = ((size_t)b * KK + k) * TR + tra;
                g_ass_hi[o] = h; g_ass_lo[o] = l;
            }
            if (trb < TR) {
                __nv_bfloat16 h, l; split_bf(ab, h, l);
                size_t o = ((size_t)b * KK + k) * TR + trb;
                g_ass_hi[o] = h; g_ass_lo[o] = l;
            }
        }
    }
#pragma unroll
    for (int n = 0; n < 8; n++) {
#pragma unroll
        for (int i = 0; i < 2; i++) {
            const int k = n * 8 + 2 * t + i;
            float sum = cacc[n][i] + cacc[n][2 + i];
            sum += __shfl_xor_sync(0xffffffffu, sum, 4);
            sum += __shfl_xor_sync(0xffffffffu, sum, 8);
            sum += __shfl_xor_sync(0xffffffffu, sum, 16);
            if (g == 0) atomicAdd(&sAs[k], sum);
        }
    }
    __syncthreads();
    if (tid < 64) atomicAdd(&g_asum[b * 64 + tid], sAs[tid]);
}

// ================= GEMM2: vlad_partial[b,k,d] += sum_tr a*x =================
// grid (32, 4, 7), block 256. 7 even tr-splits of 7 chunks. Register prefetch.
#define X2ROW 72
#define G2_XH 0
#define G2_XL (128 * X2ROW)
#define G2_AH (2 * 128 * X2ROW)
#define G2_AL (2 * 128 * X2ROW + 64 * X2ROW)
#define G2_END (2 * 128 * X2ROW + 2 * 64 * X2ROW)
#define G2_SMEM (G2_END * 2 + 256)

__global__ __launch_bounds__(256) void k_g2(const float* __restrict__ x) {
    uint16_t* S = (uint16_t*)smx;
    const uint32_t sbb = smem_u32(S);
    const int tid = threadIdx.x, wid = tid >> 5, lane = tid & 31;
    const int g = lane >> 2, t = lane & 3;
    const int b = blockIdx.x, d0 = blockIdx.y * 128, sp = blockIdx.z;
    const int c0 = sp * 7;
    const int c1 = c0 + 7;

    float cacc[8][4];
#pragma unroll
    for (int n = 0; n < 8; n++)
#pragma unroll
        for (int i = 0; i < 4; i++) cacc[n][i] = 0.f;

    const uint32_t aoff = (uint32_t)((wid * 16 + (lane & 15)) * X2ROW + (lane >> 4) * 8) * 2;
    const int L = lane & 15;
    const uint32_t boff = (uint32_t)((L & 7) * X2ROW + (L >> 3) * 8) * 2;

    const int xrow_lo = tid >> 4, xc4 = tid & 15;
    const int arow_lo = tid >> 3, ac8 = tid & 7;

    float4 rx[8];
    uint4 rah[2], ral[2];

    auto loadc = [&](int c) {
        const int trn = c * 64;
#pragma unroll
        for (int j = 0; j < 8; j++)
            rx[j] = *(const float4*)(x + ((size_t)b * DD + d0 + xrow_lo + j * 16) * TR + trn + xc4 * 4);
#pragma unroll
        for (int j = 0; j < 2; j++) {
            size_t src = ((size_t)b * KK + arow_lo + j * 32) * TR + trn + ac8 * 8;
            rah[j] = *(const uint4*)(g_ass_hi + src);
            ral[j] = *(const uint4*)(g_ass_lo + src);
        }
    };

    loadc(c0);

    for (int c = c0; c < c1; c++) {
        __syncthreads();
#pragma unroll
        for (int j = 0; j < 8; j++) {
            uint2 vh, vl; split4(rx[j], vh, vl);
            *(uint2*)(S + G2_XH + (xrow_lo + j * 16) * X2ROW + xc4 * 4) = vh;
            *(uint2*)(S + G2_XL + (xrow_lo + j * 16) * X2ROW + xc4 * 4) = vl;
        }
#pragma unroll
        for (int j = 0; j < 2; j++) {
            int row = arow_lo + j * 32;
            *(uint2*)(S + G2_AH + row * X2ROW + ac8 * 8)     = make_uint2(rah[j].x, rah[j].y);
            *(uint2*)(S + G2_AH + row * X2ROW + ac8 * 8 + 4) = make_uint2(rah[j].z, rah[j].w);
            *(uint2*)(S + G2_AL + row * X2ROW + ac8 * 8)     = make_uint2(ral[j].x, ral[j].y);
            *(uint2*)(S + G2_AL + row * X2ROW + ac8 * 8 + 4) = make_uint2(ral[j].z, ral[j].w);
        }
        __syncthreads();

        if (c + 1 < c1) loadc(c + 1);

#pragma unroll
        for (int s = 0; s < 4; s++) {
            uint32_t ah[4], al[4];
            ldmx4(ah, sbb + G2_XH * 2 + (uint32_t)(s * 16) * 2 + aoff);
            ldmx4(al, sbb + G2_XL * 2 + (uint32_t)(s * 16) * 2 + aoff);
#pragma unroll
            for (int n = 0; n < 8; n++) {
                uint32_t bh[2], bl[2];
                uint32_t bb = (uint32_t)(n * 8 * X2ROW + s * 16) * 2 + boff;
                ldmx2(bh, sbb + G2_AH * 2 + bb);
                ldmx2(bl, sbb + G2_AL * 2 + bb);
                mma_bf16(cacc[n], ah, bh);
                mma_bf16(cacc[n], ah, bl);
                mma_bf16(cacc[n], al, bh);
            }
        }
    }

    const int da = d0 + wid * 16 + g;
    const int db = da + 8;
#pragma unroll
    for (int n = 0; n < 8; n++) {
#pragma unroll
        for (int i = 0; i < 2; i++) {
            const int k = n * 8 + 2 * t + i;
            atomicAdd(&g_vlad[((size_t)b * KK + k) * DD + da], cacc[n][i]);
            atomicAdd(&g_vlad[((size_t)b * KK + k) * DD + db], cacc[n][2 + i]);
        }
    }
}

// ================= K3: subtract a_sum*centroid, intra-norm, per-b sumsq =================
__global__ __launch_bounds__(128) void k_intranorm(const float* __restrict__ centroids) {
    __shared__ float sred[4];
    const int row = blockIdx.x;
    const int tid = threadIdx.x, lane = tid & 31, w = tid >> 5;
    const float as = g_asum[row];
    float4* v = (float4*)(g_vlad + (size_t)row * 512);
    float4 val = v[tid];
    const float4 cv = ((const float4*)(centroids + (size_t)(row & 63) * DD))[tid];
    val.x -= as * cv.x; val.y -= as * cv.y; val.z -= as * cv.z; val.w -= as * cv.w;
    float ss = val.x * val.x + val.y * val.y + val.z * val.z + val.w * val.w;
    ss += __shfl_xor_sync(0xffffffffu, ss, 16);
    ss += __shfl_xor_sync(0xffffffffu, ss, 8);
    ss += __shfl_xor_sync(0xffffffffu, ss, 4);
    ss += __shfl_xor_sync(0xffffffffu, ss, 2);
    ss += __shfl_xor_sync(0xffffffffu, ss, 1);
    if (lane == 0) sred[w] = ss;
    __syncthreads();
    float tot = sred[0] + sred[1] + sred[2] + sred[3];
    float scale = 1.f / fmaxf(sqrtf(tot), 1e-12f);
    val.x *= scale; val.y *= scale; val.z *= scale; val.w *= scale;
    v[tid] = val;
    if (tid == 0) atomicAdd(&g_bsq[row >> 6], tot * scale * scale);
}

// ================= K4: reduction GEMM on HMMA (register prefetch, static smem) =================
#define RROW 72
__global__ __launch_bounds__(256) void k_reduce(const float* __restrict__ red_w) {
    __shared__ uint16_t WH[64 * RROW], WL[64 * RROW];
    __shared__ uint16_t VH[32 * RROW], VL[32 * RROW];
    __shared__ float sBS[32];
    const int tid = threadIdx.x, wid = tid >> 5, lane = tid & 31;
    const int g = lane >> 2, t = lane & 3;
    const int o0 = blockIdx.x * 64;
    const int j0 = blockIdx.y * 2048;
    const int warp_m = (wid & 3) * 16;
    const int warp_n = (wid >> 2) * 16;

    if (tid < 32) sBS[tid] = 1.f / fmaxf(sqrtf(g_bsq[tid]), 1e-12f);
    __syncthreads();

    float cacc[2][4];
#pragma unroll
    for (int n = 0; n < 2; n++)
#pragma unroll
        for (int i = 0; i < 4; i++) cacc[n][i] = 0.f;

    const uint32_t whb = smem_u32(WH), wlb = smem_u32(WL);
    const uint32_t vhb = smem_u32(VH), vlb = smem_u32(VL);
    const uint32_t aoff = (uint32_t)((warp_m + (lane & 15)) * RROW + (lane >> 4) * 8) * 2;
    const uint32_t boff = (uint32_t)((warp_n + (lane & 7) + ((lane >> 4) & 1) * 8) * RROW +
                                     ((lane >> 3) & 1) * 8) * 2;

    const int wrow_lo = tid >> 4, wc4 = tid & 15;

    float4 rw[4], rv[2];
#pragma unroll
    for (int j = 0; j < 4; j++)
        rw[j] = *(const float4*)(red_w + (size_t)(o0 + wrow_lo + j * 16) * KD + j0 + wc4 * 4);
#pragma unroll
    for (int j = 0; j < 2; j++)
        rv[j] = *(const float4*)(g_vlad + (size_t)(wrow_lo + j * 16) * KD + j0 + wc4 * 4);

    for (int c = 0; c < 32; c++) {
        __syncthreads();
#pragma unroll
        for (int j = 0; j < 4; j++) {
            uint2 vh, vl; split4(rw[j], vh, vl);
            *(uint2*)(WH + (wrow_lo + j * 16) * RROW + wc4 * 4) = vh;
            *(uint2*)(WL + (wrow_lo + j * 16) * RROW + wc4 * 4) = vl;
        }
#pragma unroll
        for (int j = 0; j < 2; j++) {
            int row = wrow_lo + j * 16;
            float bs = sBS[row];
            float4 vv = rv[j];
            vv.x *= bs; vv.y *= bs; vv.z *= bs; vv.w *= bs;
            uint2 vh, vl; split4(vv, vh, vl);
            *(uint2*)(VH + row * RROW + wc4 * 4) = vh;
            *(uint2*)(VL + row * RROW + wc4 * 4) = vl;
        }
        __syncthreads();

        if (c + 1 < 32) {
            const int jc = j0 + (c + 1) * 64;
#pragma unroll
            for (int j = 0; j < 4; j++)
                rw[j] = *(const float4*)(red_w + (size_t)(o0 + wrow_lo + j * 16) * KD + jc + wc4 * 4);
#pragma unroll
            for (int j = 0; j < 2; j++)
                rv[j] = *(const float4*)(g_vlad + (size_t)(wrow_lo + j * 16) * KD + jc + wc4 * 4);
        }

#pragma unroll
        for (int ks = 0; ks < 4; ks++) {
            const uint32_t co = (uint32_t)(ks * 16) * 2;
            uint32_t ah[4], al[4], bh[4], bl[4];
            ldmx4(ah, whb + co + aoff);
            ldmx4(al, wlb + co + aoff);
            ldmx4(bh, vhb + co + boff);
            ldmx4(bl, vlb + co + boff);
            mma_bf16(cacc[0], ah, bh);     mma_bf16(cacc[0], ah, bl);
            mma_bf16(cacc[0], al, bh);
            mma_bf16(cacc[1], ah, bh + 2); mma_bf16(cacc[1], ah, bl + 2);
            mma_bf16(cacc[1], al, bh + 2);
        }
    }

#pragma unroll
    for (int nt = 0; nt < 2; nt++) {
        const int bcol = warp_n + nt * 8 + 2 * t;
        const int oa = o0 + warp_m + g;
        atomicAdd(&g_outpre[(size_t)bcol * OUTN + oa],           cacc[nt][0]);
        atomicAdd(&g_outpre[(size_t)(bcol + 1) * OUTN + oa],     cacc[nt][1]);
        atomicAdd(&g_outpre[(size_t)bcol * OUTN + oa + 8],       cacc[nt][2]);
        atomicAdd(&g_outpre[(size_t)(bcol + 1) * OUTN + oa + 8], cacc[nt][3]);
    }
}

// ================= K5: LayerNorm =================
__global__ __launch_bounds__(256) void k_ln(
    const float* __restrict__ gamma, const float* __restrict__ beta,
    float* __restrict__ out)
{
    __shared__ float sred[8];
    const int b = blockIdx.x, tid = threadIdx.x, lane = tid & 31, w = tid >> 5;
    float4 v = ((const float4*)(g_outpre + (size_t)b * OUTN))[tid];
    float s = v.x + v.y + v.z + v.w;
    s += __shfl_xor_sync(0xffffffffu, s, 16);
    s += __shfl_xor_sync(0xffffffffu, s, 8);
    s += __shfl_xor_sync(0xffffffffu, s, 4);
    s += __shfl_xor_sync(0xffffffffu, s, 2);
    s += __shfl_xor_sync(0xffffffffu, s, 1);
    if (lane == 0) sred[w] = s;
    __syncthreads();
    float tot = 0.f;
#pragma unroll
    for (int i = 0; i < 8; i++) tot += sred[i];
    const float mu = tot * (1.f / 1024.f);
    float dx0 = v.x - mu, dx1 = v.y - mu, dx2 = v.z - mu, dx3 = v.w - mu;
    float vs = dx0 * dx0 + dx1 * dx1 + dx2 * dx2 + dx3 * dx3;
    vs += __shfl_xor_sync(0xffffffffu, vs, 16);
    vs += __shfl_xor_sync(0xffffffffu, vs, 8);
    vs += __shfl_xor_sync(0xffffffffu, vs, 4);
    vs += __shfl_xor_sync(0xffffffffu, vs, 2);
    vs += __shfl_xor_sync(0xffffffffu, vs, 1);
    __syncthreads();
    if (lane == 0) sred[w] = vs;
    __syncthreads();
    float vtot = 0.f;
#pragma unroll
    for (int i = 0; i < 8; i++) vtot += sred[i];
    const float inv = 1.f / sqrtf(vtot * (1.f / 1024.f) + 1e-5f);
    float4 gm = ((const float4*)gamma)[tid];
    float4 be = ((const float4*)beta)[tid];
    float4 r;
    r.x = dx0 * inv * gm.x + be.x;
    r.y = dx1 * inv * gm.y + be.y;
    r.z = dx2 * inv * gm.z + be.z;
    r.w = dx3 * inv * gm.w + be.w;
    ((float4*)(out + (size_t)b * OUTN))[tid] = r;
}

// ================= launch =================
extern "C" void kernel_launch(void* const* d_in, const int* in_sizes, int n_in,
                              void* d_out, int out_size)
{
    const float* x         = (const float*)d_in[0];
    const int*   mask      = (const int*)d_in[1];
    const float* centroids = (const float*)d_in[2];
    const float* conv_w    = (const float*)d_in[3];
    const float* red_w     = (const float*)d_in[4];
    const float* gamma     = (const float*)d_in[5];
    const float* beta      = (const float*)d_in[6];
    float* out = (float*)d_out;

    cudaFuncSetAttribute(k_g1, cudaFuncAttributeMaxDynamicSharedMemorySize, G1_SMEM);
    cudaFuncSetAttribute(k_g2, cudaFuncAttributeMaxDynamicSharedMemorySize, G2_SMEM);

    k_zero<<<BB * KD / 256, 256>>>();
    k_g1<<<dim3(BB, 25), 256, G1_SMEM>>>(x, mask, conv_w);
    k_g2<<<dim3(BB, 4, 7), 256, G2_SMEM>>>(x);
    k_intranorm<<<BB * KK, 128>>>(centroids);
    k_reduce<<<dim3(16, 16), 256>>>(red_w);
    k_ln<<<BB, 256>>>(gamma, beta, out);
}

// round 12
// speedup vs baseline: 1.1674x; 1.1663x over previous
#include <cuda_runtime.h>
#include <cuda_bf16.h>
#include <math.h>
#include <cstdint>

#define BB 32
#define DD 512
#define TT 64
#define RR 49
#define TR 3136
#define KK 64
#define OUTN 1024
#define KD 32768

// ================= mma / ldmatrix =================
__device__ __forceinline__ void mma_bf16(float* c, const uint32_t* a, const uint32_t* b) {
    asm volatile(
        "mma.sync.aligned.m16n8k16.row.col.f32.bf16.bf16.f32 "
        "{%0,%1,%2,%3}, {%4,%5,%6,%7}, {%8,%9}, {%0,%1,%2,%3};"
        : "+f"(c[0]), "+f"(c[1]), "+f"(c[2]), "+f"(c[3])
        : "r"(a[0]), "r"(a[1]), "r"(a[2]), "r"(a[3]), "r"(b[0]), "r"(b[1]));
}
__device__ __forceinline__ void ldmx4(uint32_t* r, uint32_t a) {
    asm volatile("ldmatrix.sync.aligned.m8n8.x4.shared.b16 {%0,%1,%2,%3}, [%4];"
                 : "=r"(r[0]), "=r"(r[1]), "=r"(r[2]), "=r"(r[3]) : "r"(a));
}
__device__ __forceinline__ void ldmx4t(uint32_t* r, uint32_t a) {
    asm volatile("ldmatrix.sync.aligned.m8n8.x4.trans.shared.b16 {%0,%1,%2,%3}, [%4];"
                 : "=r"(r[0]), "=r"(r[1]), "=r"(r[2]), "=r"(r[3]) : "r"(a));
}
__device__ __forceinline__ void ldmx2(uint32_t* r, uint32_t a) {
    asm volatile("ldmatrix.sync.aligned.m8n8.x2.shared.b16 {%0,%1}, [%2];"
                 : "=r"(r[0]), "=r"(r[1]) : "r"(a));
}
__device__ __forceinline__ uint32_t smem_u32(const void* p) {
    uint32_t a;
    asm("{ .reg .u64 t; cvta.to.shared.u64 t, %1; cvt.u32.u64 %0, t; }" : "=r"(a) : "l"(p));
    return a;
}
__device__ __forceinline__ void split_bf(float f, __nv_bfloat16& h, __nv_bfloat16& l) {
    h = __float2bfloat16(f);
    l = __float2bfloat16(f - __bfloat162float(h));
}
__device__ __forceinline__ uint32_t pkbf(__nv_bfloat16 a, __nv_bfloat16 b) {
    return (uint32_t)__bfloat16_as_ushort(a) | ((uint32_t)__bfloat16_as_ushort(b) << 16);
}
__device__ __forceinline__ uint32_t prmt(uint32_t a, uint32_t b, uint32_t sel) {
    uint32_t r; asm("prmt.b32 %0, %1, %2, %3;" : "=r"(r) : "r"(a), "r"(b), "r"(sel)); return r;
}
// Truncation split: hi = top 16 bits (exact bf16), lo = rn(f - hi). hi+lo == f to ~2^-17.
__device__ __forceinline__ void split4(float4 v, uint2& vh, uint2& vl) {
    uint32_t ux = __float_as_uint(v.x), uy = __float_as_uint(v.y);
    uint32_t uz = __float_as_uint(v.z), uw = __float_as_uint(v.w);
    vh.x = prmt(ux, uy, 0x7632);          // bf16(x) | bf16(y)<<16 (truncated)
    vh.y = prmt(uz, uw, 0x7632);
    float lx = v.x - __uint_as_float(ux & 0xffff0000u);
    float ly = v.y - __uint_as_float(uy & 0xffff0000u);
    float lz = v.z - __uint_as_float(uz & 0xffff0000u);
    float lw = v.w - __uint_as_float(uw & 0xffff0000u);
    asm("cvt.rn.bf16x2.f32 %0, %1, %2;" : "=r"(vl.x) : "f"(ly), "f"(lx));
    asm("cvt.rn.bf16x2.f32 %0, %1, %2;" : "=r"(vl.y) : "f"(lw), "f"(lz));
}

// ================= scratch =================
__device__ __align__(256) __nv_bfloat16 g_ass_hi[(size_t)BB * KK * TR];
__device__ __align__(256) __nv_bfloat16 g_ass_lo[(size_t)BB * KK * TR];
__device__ __align__(256) float g_asum[BB * KK];
__device__ __align__(256) float g_vlad[BB * KD];
__device__ __align__(256) float g_bsq[BB];
__device__ __align__(256) float g_outpre[BB * OUTN];

__global__ void k_zero() {
    int i = blockIdx.x * 256 + threadIdx.x;
    g_vlad[i] = 0.f;
    if (i < BB * OUTN) g_outpre[i] = 0.f;
    if (i < BB * KK)   g_asum[i]   = 0.f;
    if (i < BB)        g_bsq[i]    = 0.f;
}

extern __shared__ unsigned char smx[];

// ================= GEMM1: logits -> softmax -> assign + a_sum =================
// grid (32, 25), block 256 (8 warps). Register prefetch one chunk ahead; single smem buffer.
#define X1ROW 136
#define W1ROW 72
#define G1_XH 0
#define G1_XL (64 * X1ROW)
#define G1_WH (2 * 64 * X1ROW)
#define G1_WL (2 * 64 * X1ROW + 64 * W1ROW)
#define G1_END (2 * 64 * X1ROW + 2 * 64 * W1ROW)
#define G1_SMEM (G1_END * 2 + 256)

__global__ __launch_bounds__(256) void k_g1(const float* __restrict__ x,
                                            const int* __restrict__ mask,
                                            const float* __restrict__ conv_w) {
    uint16_t* S = (uint16_t*)smx;
    float* sAs = (float*)(S + G1_END);
    const uint32_t sb = smem_u32(S);
    const int tid = threadIdx.x, wid = tid >> 5, lane = tid & 31;
    const int g = lane >> 2, t = lane & 3;
    const int b = blockIdx.x, tr0 = blockIdx.y * 128;

    if (tid < 64) sAs[tid] = 0.f;

    float cacc[8][4];
#pragma unroll
    for (int n = 0; n < 8; n++)
#pragma unroll
        for (int i = 0; i < 4; i++) cacc[n][i] = 0.f;

    const uint32_t aoff = (uint32_t)(((lane >> 4) * 8 + (lane & 7)) * X1ROW +
                                     wid * 16 + ((lane >> 3) & 1) * 8) * 2;
    const int L = lane & 15;
    const uint32_t boff = (uint32_t)((L & 7) * W1ROW + (L >> 3) * 8) * 2;

    const int xrow[8] = { tid >> 5, (tid + 256) >> 5, (tid + 512) >> 5, (tid + 768) >> 5,
                          (tid + 1024) >> 5, (tid + 1280) >> 5, (tid + 1536) >> 5, (tid + 1792) >> 5 };
    const int xc4 = tid & 31;
    const int xtr = tr0 + xc4 * 4;
    const bool xok = (xtr < TR);

    float4 rx[8];
#pragma unroll
    for (int j = 0; j < 8; j++)
        rx[j] = xok ? *(const float4*)(x + ((size_t)b * DD + xrow[j]) * TR + xtr)
                    : make_float4(0.f, 0.f, 0.f, 0.f);

    for (int q = 0; q < 8; q++) {
        __syncthreads();
#pragma unroll
        for (int j = 0; j < 8; j++) {
            uint2 vh, vl; split4(rx[j], vh, vl);
            *(uint2*)(S + G1_XH + xrow[j] * X1ROW + xc4 * 4) = vh;
            *(uint2*)(S + G1_XL + xrow[j] * X1ROW + xc4 * 4) = vl;
        }
        for (int u = tid; u < 1024; u += 256) {          // W chunk (L2-hot)
            int row = u >> 4, c4 = u & 15;
            float4 wv = *(const float4*)(conv_w + row * DD + q * 64 + c4 * 4);
            uint2 vh, vl; split4(wv, vh, vl);
            *(uint2*)(S + G1_WH + row * W1ROW + c4 * 4) = vh;
            *(uint2*)(S + G1_WL + row * W1ROW + c4 * 4) = vl;
        }
        __syncthreads();

        if (q < 7) {                                     // prefetch next chunk
#pragma unroll
            for (int j = 0; j < 8; j++)
                rx[j] = xok ? *(const float4*)(x + ((size_t)b * DD + (q + 1) * 64 + xrow[j]) * TR + xtr)
                            : make_float4(0.f, 0.f, 0.f, 0.f);
        }

#pragma unroll
        for (int s = 0; s < 4; s++) {
            uint32_t ah[4], al[4];
            ldmx4t(ah, sb + G1_XH * 2 + (uint32_t)(s * 16 * X1ROW) * 2 + aoff);
            ldmx4t(al, sb + G1_XL * 2 + (uint32_t)(s * 16 * X1ROW) * 2 + aoff);
#pragma unroll
            for (int n = 0; n < 8; n++) {
                uint32_t bh[2], bl[2];
                uint32_t bb = (uint32_t)(n * 8 * W1ROW + s * 16) * 2 + boff;
                ldmx2(bh, sb + G1_WH * 2 + bb);
                ldmx2(bl, sb + G1_WL * 2 + bb);
                mma_bf16(cacc[n], ah, bh);
                mma_bf16(cacc[n], ah, bl);
                mma_bf16(cacc[n], al, bh);
            }
        }
    }

    const int tra = tr0 + wid * 16 + g;
    const int trb = tra + 8;
    float ma = -1e30f, mb = -1e30f;
#pragma unroll
    for (int n = 0; n < 8; n++) {
        ma = fmaxf(ma, fmaxf(cacc[n][0], cacc[n][1]));
        mb = fmaxf(mb, fmaxf(cacc[n][2], cacc[n][3]));
    }
    ma = fmaxf(ma, __shfl_xor_sync(0xffffffffu, ma, 1));
    ma = fmaxf(ma, __shfl_xor_sync(0xffffffffu, ma, 2));
    mb = fmaxf(mb, __shfl_xor_sync(0xffffffffu, mb, 1));
    mb = fmaxf(mb, __shfl_xor_sync(0xffffffffu, mb, 2));
    float sa = 0.f, sb2 = 0.f;
#pragma unroll
    for (int n = 0; n < 8; n++) {
        cacc[n][0] = __expf(cacc[n][0] - ma); sa += cacc[n][0];
        cacc[n][1] = __expf(cacc[n][1] - ma); sa += cacc[n][1];
        cacc[n][2] = __expf(cacc[n][2] - mb); sb2 += cacc[n][2];
        cacc[n][3] = __expf(cacc[n][3] - mb); sb2 += cacc[n][3];
    }
    sa  += __shfl_xor_sync(0xffffffffu, sa, 1);
    sa  += __shfl_xor_sync(0xffffffffu, sa, 2);
    sb2 += __shfl_xor_sync(0xffffffffu, sb2, 1);
    sb2 += __shfl_xor_sync(0xffffffffu, sb2, 2);
    const float mva = (tra < TR) ? (float)mask[b * TT + tra / RR] : 0.f;
    const float mvb = (trb < TR) ? (float)mask[b * TT + trb / RR] : 0.f;
    const float inva = mva / sa, invb = mvb / sb2;

#pragma unroll
    for (int n = 0; n < 8; n++) {
#pragma unroll
        for (int i = 0; i < 2; i++) {
            const int k = n * 8 + 2 * t + i;
            float aa = cacc[n][i] * inva;
            float ab = cacc[n][2 + i] * invb;
            if (tra < TR) {
                __nv_bfloat16 h, l; split_bf(aa, h, l);
                size_t o = ((size_t)b * KK + k) * TR + tra;
                g_ass_hi[o] = h; g_ass_lo[o] = l;
            }
            if (trb < TR) {
                __nv_bfloat16 h, l; split_bf(ab, h, l);
                size_t o = ((size_t)b * KK + k) * TR + trb;
                g_ass_hi[o] = h; g_ass_lo[o] = l;
            }
            float sum = aa + ab;
            sum += __shfl_xor_sync(0xffffffffu, sum, 4);
            sum += __shfl_xor_sync(0xffffffffu, sum, 8);
            sum += __shfl_xor_sync(0xffffffffu, sum, 16);
            if (g == 0) atomicAdd(&sAs[k], sum);
        }
    }
    __syncthreads();
    if (tid < 64) atomicAdd(&g_asum[b * 64 + tid], sAs[tid]);
}

// ================= GEMM2: vlad_partial[b,k,d] += sum_tr a*x =================
// grid (32, 4, 4), block 256. Register prefetch one chunk ahead.
#define X2ROW 72
#define G2_XH 0
#define G2_XL (128 * X2ROW)
#define G2_AH (2 * 128 * X2ROW)
#define G2_AL (2 * 128 * X2ROW + 64 * X2ROW)
#define G2_END (2 * 128 * X2ROW + 2 * 64 * X2ROW)
#define G2_SMEM (G2_END * 2 + 256)

__global__ __launch_bounds__(256) void k_g2(const float* __restrict__ x) {
    uint16_t* S = (uint16_t*)smx;
    const uint32_t sbb = smem_u32(S);
    const int tid = threadIdx.x, wid = tid >> 5, lane = tid & 31;
    const int g = lane >> 2, t = lane & 3;
    const int b = blockIdx.x, d0 = blockIdx.y * 128, sp = blockIdx.z;
    const int c0 = sp ? 12 * sp + 1 : 0;
    const int c1 = (sp == 3) ? 49 : 12 * (sp + 1) + 1;

    float cacc[8][4];
#pragma unroll
    for (int n = 0; n < 8; n++)
#pragma unroll
        for (int i = 0; i < 4; i++) cacc[n][i] = 0.f;

    const uint32_t aoff = (uint32_t)((wid * 16 + (lane & 15)) * X2ROW + (lane >> 4) * 8) * 2;
    const int L = lane & 15;
    const uint32_t boff = (uint32_t)((L & 7) * X2ROW + (L >> 3) * 8) * 2;

    const int xrow_lo = tid >> 4, xc4 = tid & 15;
    const int arow_lo = tid >> 3, ac8 = tid & 7;

    float4 rx[8];
    uint4 rah[2], ral[2];

    auto loadc = [&](int c) {
        const int trn = c * 64;
#pragma unroll
        for (int j = 0; j < 8; j++)
            rx[j] = *(const float4*)(x + ((size_t)b * DD + d0 + xrow_lo + j * 16) * TR + trn + xc4 * 4);
#pragma unroll
        for (int j = 0; j < 2; j++) {
            size_t src = ((size_t)b * KK + arow_lo + j * 32) * TR + trn + ac8 * 8;
            rah[j] = *(const uint4*)(g_ass_hi + src);
            ral[j] = *(const uint4*)(g_ass_lo + src);
        }
    };

    loadc(c0);

    for (int c = c0; c < c1; c++) {
        __syncthreads();
#pragma unroll
        for (int j = 0; j < 8; j++) {
            uint2 vh, vl; split4(rx[j], vh, vl);
            *(uint2*)(S + G2_XH + (xrow_lo + j * 16) * X2ROW + xc4 * 4) = vh;
            *(uint2*)(S + G2_XL + (xrow_lo + j * 16) * X2ROW + xc4 * 4) = vl;
        }
#pragma unroll
        for (int j = 0; j < 2; j++) {
            int row = arow_lo + j * 32;
            *(uint2*)(S + G2_AH + row * X2ROW + ac8 * 8)     = make_uint2(rah[j].x, rah[j].y);
            *(uint2*)(S + G2_AH + row * X2ROW + ac8 * 8 + 4) = make_uint2(rah[j].z, rah[j].w);
            *(uint2*)(S + G2_AL + row * X2ROW + ac8 * 8)     = make_uint2(ral[j].x, ral[j].y);
            *(uint2*)(S + G2_AL + row * X2ROW + ac8 * 8 + 4) = make_uint2(ral[j].z, ral[j].w);
        }
        __syncthreads();

        if (c + 1 < c1) loadc(c + 1);

#pragma unroll
        for (int s = 0; s < 4; s++) {
            uint32_t ah[4], al[4];
            ldmx4(ah, sbb + G2_XH * 2 + (uint32_t)(s * 16) * 2 + aoff);
            ldmx4(al, sbb + G2_XL * 2 + (uint32_t)(s * 16) * 2 + aoff);
#pragma unroll
            for (int n = 0; n < 8; n++) {
                uint32_t bh[2], bl[2];
                uint32_t bb = (uint32_t)(n * 8 * X2ROW + s * 16) * 2 + boff;
                ldmx2(bh, sbb + G2_AH * 2 + bb);
                ldmx2(bl, sbb + G2_AL * 2 + bb);
                mma_bf16(cacc[n], ah, bh);
                mma_bf16(cacc[n], ah, bl);
                mma_bf16(cacc[n], al, bh);
            }
        }
    }

    const int da = d0 + wid * 16 + g;
    const int db = da + 8;
#pragma unroll
    for (int n = 0; n < 8; n++) {
#pragma unroll
        for (int i = 0; i < 2; i++) {
            const int k = n * 8 + 2 * t + i;
            atomicAdd(&g_vlad[((size_t)b * KK + k) * DD + da], cacc[n][i]);
            atomicAdd(&g_vlad[((size_t)b * KK + k) * DD + db], cacc[n][2 + i]);
        }
    }
}

// ================= K3: subtract a_sum*centroid, intra-norm, per-b sumsq =================
__global__ __launch_bounds__(128) void k_intranorm(const float* __restrict__ centroids) {
    __shared__ float sred[4];
    const int row = blockIdx.x;
    const int tid = threadIdx.x, lane = tid & 31, w = tid >> 5;
    const float as = g_asum[row];
    float4* v = (float4*)(g_vlad + (size_t)row * 512);
    float4 val = v[tid];
    const float4 cv = ((const float4*)(centroids + (size_t)(row & 63) * DD))[tid];
    val.x -= as * cv.x; val.y -= as * cv.y; val.z -= as * cv.z; val.w -= as * cv.w;
    float ss = val.x * val.x + val.y * val.y + val.z * val.z + val.w * val.w;
    ss += __shfl_xor_sync(0xffffffffu, ss, 16);
    ss += __shfl_xor_sync(0xffffffffu, ss, 8);
    ss += __shfl_xor_sync(0xffffffffu, ss, 4);
    ss += __shfl_xor_sync(0xffffffffu, ss, 2);
    ss += __shfl_xor_sync(0xffffffffu, ss, 1);
    if (lane == 0) sred[w] = ss;
    __syncthreads();
    float tot = sred[0] + sred[1] + sred[2] + sred[3];
    float scale = 1.f / fmaxf(sqrtf(tot), 1e-12f);
    val.x *= scale; val.y *= scale; val.z *= scale; val.w *= scale;
    v[tid] = val;
    if (tid == 0) atomicAdd(&g_bsq[row >> 6], tot * scale * scale);
}

// ================= K4: reduction GEMM on HMMA (register prefetch, static smem) =================
#define RROW 72
__global__ __launch_bounds__(256) void k_reduce(const float* __restrict__ red_w) {
    __shared__ uint16_t WH[64 * RROW], WL[64 * RROW];
    __shared__ uint16_t VH[32 * RROW], VL[32 * RROW];
    __shared__ float sBS[32];
    const int tid = threadIdx.x, wid = tid >> 5, lane = tid & 31;
    const int g = lane >> 2, t = lane & 3;
    const int o0 = blockIdx.x * 64;
    const int j0 = blockIdx.y * 2048;
    const int warp_m = (wid & 3) * 16;
    const int warp_n = (wid >> 2) * 16;

    if (tid < 32) sBS[tid] = 1.f / fmaxf(sqrtf(g_bsq[tid]), 1e-12f);
    __syncthreads();

    float cacc[2][4];
#pragma unroll
    for (int n = 0; n < 2; n++)
#pragma unroll
        for (int i = 0; i < 4; i++) cacc[n][i] = 0.f;

    const uint32_t whb = smem_u32(WH), wlb = smem_u32(WL);
    const uint32_t vhb = smem_u32(VH), vlb = smem_u32(VL);
    const uint32_t aoff = (uint32_t)((warp_m + (lane & 15)) * RROW + (lane >> 4) * 8) * 2;
    const uint32_t boff = (uint32_t)((warp_n + (lane & 7) + ((lane >> 4) & 1) * 8) * RROW +
                                     ((lane >> 3) & 1) * 8) * 2;

    const int wrow_lo = tid >> 4, wc4 = tid & 15;

    float4 rw[4], rv[2];
#pragma unroll
    for (int j = 0; j < 4; j++)
        rw[j] = *(const float4*)(red_w + (size_t)(o0 + wrow_lo + j * 16) * KD + j0 + wc4 * 4);
#pragma unroll
    for (int j = 0; j < 2; j++)
        rv[j] = *(const float4*)(g_vlad + (size_t)(wrow_lo + j * 16) * KD + j0 + wc4 * 4);

    for (int c = 0; c < 32; c++) {
        __syncthreads();
#pragma unroll
        for (int j = 0; j < 4; j++) {
            uint2 vh, vl; split4(rw[j], vh, vl);
            *(uint2*)(WH + (wrow_lo + j * 16) * RROW + wc4 * 4) = vh;
            *(uint2*)(WL + (wrow_lo + j * 16) * RROW + wc4 * 4) = vl;
        }
#pragma unroll
        for (int j = 0; j < 2; j++) {
            int row = wrow_lo + j * 16;
            float bs = sBS[row];
            float4 vv = rv[j];
            vv.x *= bs; vv.y *= bs; vv.z *= bs; vv.w *= bs;
            uint2 vh, vl; split4(vv, vh, vl);
            *(uint2*)(VH + row * RROW + wc4 * 4) = vh;
            *(uint2*)(VL + row * RROW + wc4 * 4) = vl;
        }
        __syncthreads();

        if (c + 1 < 32) {
            const int jc = j0 + (c + 1) * 64;
#pragma unroll
            for (int j = 0; j < 4; j++)
                rw[j] = *(const float4*)(red_w + (size_t)(o0 + wrow_lo + j * 16) * KD + jc + wc4 * 4);
#pragma unroll
            for (int j = 0; j < 2; j++)
                rv[j] = *(const float4*)(g_vlad + (size_t)(wrow_lo + j * 16) * KD + jc + wc4 * 4);
        }

#pragma unroll
        for (int ks = 0; ks < 4; ks++) {
            const uint32_t co = (uint32_t)(ks * 16) * 2;
            uint32_t ah[4], al[4], bh[4], bl[4];
            ldmx4(ah, whb + co + aoff);
            ldmx4(al, wlb + co + aoff);
            ldmx4(bh, vhb + co + boff);
            ldmx4(bl, vlb + co + boff);
            mma_bf16(cacc[0], ah, bh);     mma_bf16(cacc[0], ah, bl);
            mma_bf16(cacc[0], al, bh);
            mma_bf16(cacc[1], ah, bh + 2); mma_bf16(cacc[1], ah, bl + 2);
            mma_bf16(cacc[1], al, bh + 2);
        }
    }

#pragma unroll
    for (int nt = 0; nt < 2; nt++) {
        const int bcol = warp_n + nt * 8 + 2 * t;
        const int oa = o0 + warp_m + g;
        atomicAdd(&g_outpre[(size_t)bcol * OUTN + oa],           cacc[nt][0]);
        atomicAdd(&g_outpre[(size_t)(bcol + 1) * OUTN + oa],     cacc[nt][1]);
        atomicAdd(&g_outpre[(size_t)bcol * OUTN + oa + 8],       cacc[nt][2]);
        atomicAdd(&g_outpre[(size_t)(bcol + 1) * OUTN + oa + 8], cacc[nt][3]);
    }
}

// ================= K5: LayerNorm =================
__global__ __launch_bounds__(256) void k_ln(
    const float* __restrict__ gamma, const float* __restrict__ beta,
    float* __restrict__ out)
{
    __shared__ float sred[8];
    const int b = blockIdx.x, tid = threadIdx.x, lane = tid & 31, w = tid >> 5;
    float4 v = ((const float4*)(g_outpre + (size_t)b * OUTN))[tid];
    float s = v.x + v.y + v.z + v.w;
    s += __shfl_xor_sync(0xffffffffu, s, 16);
    s += __shfl_xor_sync(0xffffffffu, s, 8);
    s += __shfl_xor_sync(0xffffffffu, s, 4);
    s += __shfl_xor_sync(0xffffffffu, s, 2);
    s += __shfl_xor_sync(0xffffffffu, s, 1);
    if (lane == 0) sred[w] = s;
    __syncthreads();
    float tot = 0.f;
#pragma unroll
    for (int i = 0; i < 8; i++) tot += sred[i];
    const float mu = tot * (1.f / 1024.f);
    float dx0 = v.x - mu, dx1 = v.y - mu, dx2 = v.z - mu, dx3 = v.w - mu;
    float vs = dx0 * dx0 + dx1 * dx1 + dx2 * dx2 + dx3 * dx3;
    vs += __shfl_xor_sync(0xffffffffu, vs, 16);
    vs += __shfl_xor_sync(0xffffffffu, vs, 8);
    vs += __shfl_xor_sync(0xffffffffu, vs, 4);
    vs += __shfl_xor_sync(0xffffffffu, vs, 2);
    vs += __shfl_xor_sync(0xffffffffu, vs, 1);
    __syncthreads();
    if (lane == 0) sred[w] = vs;
    __syncthreads();
    float vtot = 0.f;
#pragma unroll
    for (int i = 0; i < 8; i++) vtot += sred[i];
    const float inv = 1.f / sqrtf(vtot * (1.f / 1024.f) + 1e-5f);
    float4 gm = ((const float4*)gamma)[tid];
    float4 be = ((const float4*)beta)[tid];
    float4 r;
    r.x = dx0 * inv * gm.x + be.x;
    r.y = dx1 * inv * gm.y + be.y;
    r.z = dx2 * inv * gm.z + be.z;
    r.w = dx3 * inv * gm.w + be.w;
    ((float4*)(out + (size_t)b * OUTN))[tid] = r;
}

// ================= launch =================
extern "C" void kernel_launch(void* const* d_in, const int* in_sizes, int n_in,
                              void* d_out, int out_size)
{
    const float* x         = (const float*)d_in[0];
    const int*   mask      = (const int*)d_in[1];
    const float* centroids = (const float*)d_in[2];
    const float* conv_w    = (const float*)d_in[3];
    const float* red_w     = (const float*)d_in[4];
    const float* gamma     = (const float*)d_in[5];
    const float* beta      = (const float*)d_in[6];
    float* out = (float*)d_out;

    cudaFuncSetAttribute(k_g1, cudaFuncAttributeMaxDynamicSharedMemorySize, G1_SMEM);
    cudaFuncSetAttribute(k_g2, cudaFuncAttributeMaxDynamicSharedMemorySize, G2_SMEM);

    k_zero<<<BB * KD / 256, 256>>>();
    k_g1<<<dim3(BB, 25), 256, G1_SMEM>>>(x, mask, conv_w);
    k_g2<<<dim3(BB, 4, 4), 256, G2_SMEM>>>(x);
    k_intranorm<<<BB * KK, 128>>>(centroids);
    k_reduce<<<dim3(16, 16), 256>>>(red_w);
    k_ln<<<BB, 256>>>(gamma, beta, out);
}

// round 13
// speedup vs baseline: 1.3010x; 1.1145x over previous
#include <cuda_runtime.h>
#include <cuda_bf16.h>
#include <math.h>
#include <cstdint>

#define BB 32
#define DD 512
#define TT 64
#define RR 49
#define TR 3136
#define KK 64
#define OUTN 1024
#define KD 32768

// ================= mma / ldmatrix =================
__device__ __forceinline__ void mma_bf16(float* c, const uint32_t* a, const uint32_t* b) {
    asm volatile(
        "mma.sync.aligned.m16n8k16.row.col.f32.bf16.bf16.f32 "
        "{%0,%1,%2,%3}, {%4,%5,%6,%7}, {%8,%9}, {%0,%1,%2,%3};"
        : "+f"(c[0]), "+f"(c[1]), "+f"(c[2]), "+f"(c[3])
        : "r"(a[0]), "r"(a[1]), "r"(a[2]), "r"(a[3]), "r"(b[0]), "r"(b[1]));
}
__device__ __forceinline__ void ldmx4(uint32_t* r, uint32_t a) {
    asm volatile("ldmatrix.sync.aligned.m8n8.x4.shared.b16 {%0,%1,%2,%3}, [%4];"
                 : "=r"(r[0]), "=r"(r[1]), "=r"(r[2]), "=r"(r[3]) : "r"(a));
}
__device__ __forceinline__ void ldmx4t(uint32_t* r, uint32_t a) {
    asm volatile("ldmatrix.sync.aligned.m8n8.x4.trans.shared.b16 {%0,%1,%2,%3}, [%4];"
                 : "=r"(r[0]), "=r"(r[1]), "=r"(r[2]), "=r"(r[3]) : "r"(a));
}
__device__ __forceinline__ uint32_t smem_u32(const void* p) {
    uint32_t a;
    asm("{ .reg .u64 t; cvta.to.shared.u64 t, %1; cvt.u32.u64 %0, t; }" : "=r"(a) : "l"(p));
    return a;
}
__device__ __forceinline__ void split_bf(float f, __nv_bfloat16& h, __nv_bfloat16& l) {
    h = __float2bfloat16(f);
    l = __float2bfloat16(f - __bfloat162float(h));
}
__device__ __forceinline__ uint32_t prmt(uint32_t a, uint32_t b, uint32_t sel) {
    uint32_t r; asm("prmt.b32 %0, %1, %2, %3;" : "=r"(r) : "r"(a), "r"(b), "r"(sel)); return r;
}
// Truncation split: hi = top 16 bits (exact bf16), lo = rn(f - hi).
__device__ __forceinline__ void split4(float4 v, uint2& vh, uint2& vl) {
    uint32_t ux = __float_as_uint(v.x), uy = __float_as_uint(v.y);
    uint32_t uz = __float_as_uint(v.z), uw = __float_as_uint(v.w);
    vh.x = prmt(ux, uy, 0x7632);
    vh.y = prmt(uz, uw, 0x7632);
    float lx = v.x - __uint_as_float(ux & 0xffff0000u);
    float ly = v.y - __uint_as_float(uy & 0xffff0000u);
    float lz = v.z - __uint_as_float(uz & 0xffff0000u);
    float lw = v.w - __uint_as_float(uw & 0xffff0000u);
    asm("cvt.rn.bf16x2.f32 %0, %1, %2;" : "=r"(vl.x) : "f"(ly), "f"(lx));
    asm("cvt.rn.bf16x2.f32 %0, %1, %2;" : "=r"(vl.y) : "f"(lw), "f"(lz));
}

// ================= scratch =================
__device__ __align__(256) __nv_bfloat16 g_ass_hi[(size_t)BB * KK * TR];
__device__ __align__(256) __nv_bfloat16 g_ass_lo[(size_t)BB * KK * TR];
__device__ __align__(256) __nv_bfloat16 g_w_hi[KK * DD];
__device__ __align__(256) __nv_bfloat16 g_w_lo[KK * DD];
__device__ __align__(256) float g_asum[BB * KK];
__device__ __align__(256) float g_vlad[BB * KD];
__device__ __align__(256) float g_bsq[BB];
__device__ __align__(256) float g_outpre[BB * OUTN];

__global__ void k_zero() {
    int i = blockIdx.x * 256 + threadIdx.x;
    g_vlad[i] = 0.f;
    if (i < BB * OUTN) g_outpre[i] = 0.f;
    if (i < BB * KK)   g_asum[i]   = 0.f;
    if (i < BB)        g_bsq[i]    = 0.f;
}

// W hi/lo precompute (truncation split, same arithmetic as split4)
__global__ __launch_bounds__(256) void k_wsplit(const float* __restrict__ conv_w) {
    int i = blockIdx.x * 256 + threadIdx.x;
    if (i < KK * DD) {
        float f = conv_w[i];
        uint32_t u = __float_as_uint(f);
        uint32_t hb = u & 0xffff0000u;
        float lo = f - __uint_as_float(hb);
        g_w_hi[i] = __ushort_as_bfloat16((unsigned short)(u >> 16));
        g_w_lo[i] = __float2bfloat16(lo);
    }
}

extern __shared__ unsigned char smx[];

// ================= GEMM1: logits -> softmax -> assign + a_sum =================
// grid (32, 25), block 256. Register prefetch; B-fragments via ldmx4 n-pairs.
#define X1ROW 136
#define W1ROW 72
#define G1_XH 0
#define G1_XL (64 * X1ROW)
#define G1_WH (2 * 64 * X1ROW)
#define G1_WL (2 * 64 * X1ROW + 64 * W1ROW)
#define G1_END (2 * 64 * X1ROW + 2 * 64 * W1ROW)
#define G1_SMEM (G1_END * 2 + 256)

__global__ __launch_bounds__(256) void k_g1(const float* __restrict__ x,
                                            const int* __restrict__ mask) {
    uint16_t* S = (uint16_t*)smx;
    float* sAs = (float*)(S + G1_END);
    const uint32_t sb = smem_u32(S);
    const int tid = threadIdx.x, wid = tid >> 5, lane = tid & 31;
    const int g = lane >> 2, t = lane & 3;
    const int b = blockIdx.x, tr0 = blockIdx.y * 128;

    if (tid < 64) sAs[tid] = 0.f;

    float cacc[8][4];
#pragma unroll
    for (int n = 0; n < 8; n++)
#pragma unroll
        for (int i = 0; i < 4; i++) cacc[n][i] = 0.f;

    const uint32_t aoff = (uint32_t)(((lane >> 4) * 8 + (lane & 7)) * X1ROW +
                                     wid * 16 + ((lane >> 3) & 1) * 8) * 2;
    // ldmx4 B-pair addressing: rows (lane&7) + ((lane>>4)&1)*8, col ((lane>>3)&1)*8
    const uint32_t boff2 = (uint32_t)(((lane & 7) + ((lane >> 4) & 1) * 8) * W1ROW +
                                      ((lane >> 3) & 1) * 8) * 2;

    const int xrow[8] = { tid >> 5, (tid + 256) >> 5, (tid + 512) >> 5, (tid + 768) >> 5,
                          (tid + 1024) >> 5, (tid + 1280) >> 5, (tid + 1536) >> 5, (tid + 1792) >> 5 };
    const int xc4 = tid & 31;
    const int xtr = tr0 + xc4 * 4;
    const bool xok = (xtr < TR);
    const int wrow = tid >> 3, wc8 = tid & 7;   // W copy coords: 2 rows per thread pass

    float4 rx[8];
#pragma unroll
    for (int j = 0; j < 8; j++)
        rx[j] = xok ? *(const float4*)(x + ((size_t)b * DD + xrow[j]) * TR + xtr)
                    : make_float4(0.f, 0.f, 0.f, 0.f);

    for (int q = 0; q < 8; q++) {
        __syncthreads();
#pragma unroll
        for (int j = 0; j < 8; j++) {
            uint2 vh, vl; split4(rx[j], vh, vl);
            *(uint2*)(S + G1_XH + xrow[j] * X1ROW + xc4 * 4) = vh;
            *(uint2*)(S + G1_XL + xrow[j] * X1ROW + xc4 * 4) = vl;
        }
        // W chunk copy (bf16 precomputed): 64 rows x 64 d, 8 bf16 per uint4
#pragma unroll
        for (int j = 0; j < 2; j++) {
            int row = wrow + j * 32;
            size_t src = (size_t)row * DD + q * 64 + wc8 * 8;
            uint4 vh = *(const uint4*)(g_w_hi + src);
            uint4 vl = *(const uint4*)(g_w_lo + src);
            *(uint2*)(S + G1_WH + row * W1ROW + wc8 * 8)     = make_uint2(vh.x, vh.y);
            *(uint2*)(S + G1_WH + row * W1ROW + wc8 * 8 + 4) = make_uint2(vh.z, vh.w);
            *(uint2*)(S + G1_WL + row * W1ROW + wc8 * 8)     = make_uint2(vl.x, vl.y);
            *(uint2*)(S + G1_WL + row * W1ROW + wc8 * 8 + 4) = make_uint2(vl.z, vl.w);
        }
        __syncthreads();

        if (q < 7) {
#pragma unroll
            for (int j = 0; j < 8; j++)
                rx[j] = xok ? *(const float4*)(x + ((size_t)b * DD + (q + 1) * 64 + xrow[j]) * TR + xtr)
                            : make_float4(0.f, 0.f, 0.f, 0.f);
        }

#pragma unroll
        for (int s = 0; s < 4; s++) {
            uint32_t ah[4], al[4];
            ldmx4t(ah, sb + G1_XH * 2 + (uint32_t)(s * 16 * X1ROW) * 2 + aoff);
            ldmx4t(al, sb + G1_XL * 2 + (uint32_t)(s * 16 * X1ROW) * 2 + aoff);
#pragma unroll
            for (int np = 0; np < 4; np++) {
                uint32_t bh[4], bl[4];
                uint32_t bb = (uint32_t)(np * 16 * W1ROW + s * 16) * 2 + boff2;
                ldmx4(bh, sb + G1_WH * 2 + bb);
                ldmx4(bl, sb + G1_WL * 2 + bb);
                mma_bf16(cacc[2 * np],     ah, bh);     mma_bf16(cacc[2 * np],     ah, bl);
                mma_bf16(cacc[2 * np],     al, bh);
                mma_bf16(cacc[2 * np + 1], ah, bh + 2); mma_bf16(cacc[2 * np + 1], ah, bl + 2);
                mma_bf16(cacc[2 * np + 1], al, bh + 2);
            }
        }
    }

    const int tra = tr0 + wid * 16 + g;
    const int trb = tra + 8;
    float ma = -1e30f, mb = -1e30f;
#pragma unroll
    for (int n = 0; n < 8; n++) {
        ma = fmaxf(ma, fmaxf(cacc[n][0], cacc[n][1]));
        mb = fmaxf(mb, fmaxf(cacc[n][2], cacc[n][3]));
    }
    ma = fmaxf(ma, __shfl_xor_sync(0xffffffffu, ma, 1));
    ma = fmaxf(ma, __shfl_xor_sync(0xffffffffu, ma, 2));
    mb = fmaxf(mb, __shfl_xor_sync(0xffffffffu, mb, 1));
    mb = fmaxf(mb, __shfl_xor_sync(0xffffffffu, mb, 2));
    float sa = 0.f, sb2 = 0.f;
#pragma unroll
    for (int n = 0; n < 8; n++) {
        cacc[n][0] = __expf(cacc[n][0] - ma); sa += cacc[n][0];
        cacc[n][1] = __expf(cacc[n][1] - ma); sa += cacc[n][1];
        cacc[n][2] = __expf(cacc[n][2] - mb); sb2 += cacc[n][2];
        cacc[n][3] = __expf(cacc[n][3] - mb); sb2 += cacc[n][3];
    }
    sa  += __shfl_xor_sync(0xffffffffu, sa, 1);
    sa  += __shfl_xor_sync(0xffffffffu, sa, 2);
    sb2 += __shfl_xor_sync(0xffffffffu, sb2, 1);
    sb2 += __shfl_xor_sync(0xffffffffu, sb2, 2);
    const float mva = (tra < TR) ? (float)mask[b * TT + tra / RR] : 0.f;
    const float mvb = (trb < TR) ? (float)mask[b * TT + trb / RR] : 0.f;
    const float inva = mva / sa, invb = mvb / sb2;

#pragma unroll
    for (int n = 0; n < 8; n++) {
#pragma unroll
        for (int i = 0; i < 2; i++) {
            const int k = n * 8 + 2 * t + i;
            float aa = cacc[n][i] * inva;
            float ab = cacc[n][2 + i] * invb;
            if (tra < TR) {
                __nv_bfloat16 h, l; split_bf(aa, h, l);
                size_t o = ((size_t)b * KK + k) * TR + tra;
                g_ass_hi[o] = h; g_ass_lo[o] = l;
            }
            if (trb < TR) {
                __nv_bfloat16 h, l; split_bf(ab, h, l);
                size_t o = ((size_t)b * KK + k) * TR + trb;
                g_ass_hi[o] = h; g_ass_lo[o] = l;
            }
            float sum = aa + ab;
            sum += __shfl_xor_sync(0xffffffffu, sum, 4);
            sum += __shfl_xor_sync(0xffffffffu, sum, 8);
            sum += __shfl_xor_sync(0xffffffffu, sum, 16);
            if (g == 0) atomicAdd(&sAs[k], sum);
        }
    }
    __syncthreads();
    if (tid < 64) atomicAdd(&g_asum[b * 64 + tid], sAs[tid]);
}

// ================= GEMM2: vlad_partial[b,k,d] += sum_tr a*x =================
// grid (32, 4, 4), block 256. Register prefetch; B-fragments via ldmx4 n-pairs.
#define X2ROW 72
#define G2_XH 0
#define G2_XL (128 * X2ROW)
#define G2_AH (2 * 128 * X2ROW)
#define G2_AL (2 * 128 * X2ROW + 64 * X2ROW)
#define G2_END (2 * 128 * X2ROW + 2 * 64 * X2ROW)
#define G2_SMEM (G2_END * 2 + 256)

__global__ __launch_bounds__(256) void k_g2(const float* __restrict__ x) {
    uint16_t* S = (uint16_t*)smx;
    const uint32_t sbb = smem_u32(S);
    const int tid = threadIdx.x, wid = tid >> 5, lane = tid & 31;
    const int g = lane >> 2, t = lane & 3;
    const int b = blockIdx.x, d0 = blockIdx.y * 128, sp = blockIdx.z;
    const int c0 = sp ? 12 * sp + 1 : 0;
    const int c1 = (sp == 3) ? 49 : 12 * (sp + 1) + 1;

    float cacc[8][4];
#pragma unroll
    for (int n = 0; n < 8; n++)
#pragma unroll
        for (int i = 0; i < 4; i++) cacc[n][i] = 0.f;

    const uint32_t aoff = (uint32_t)((wid * 16 + (lane & 15)) * X2ROW + (lane >> 4) * 8) * 2;
    const uint32_t boff2 = (uint32_t)(((lane & 7) + ((lane >> 4) & 1) * 8) * X2ROW +
                                      ((lane >> 3) & 1) * 8) * 2;

    const int xrow_lo = tid >> 4, xc4 = tid & 15;
    const int arow_lo = tid >> 3, ac8 = tid & 7;

    float4 rx[8];
    uint4 rah[2], ral[2];

    auto loadc = [&](int c) {
        const int trn = c * 64;
#pragma unroll
        for (int j = 0; j < 8; j++)
            rx[j] = *(const float4*)(x + ((size_t)b * DD + d0 + xrow_lo + j * 16) * TR + trn + xc4 * 4);
#pragma unroll
        for (int j = 0; j < 2; j++) {
            size_t src = ((size_t)b * KK + arow_lo + j * 32) * TR + trn + ac8 * 8;
            rah[j] = *(const uint4*)(g_ass_hi + src);
            ral[j] = *(const uint4*)(g_ass_lo + src);
        }
    };

    loadc(c0);

    for (int c = c0; c < c1; c++) {
        __syncthreads();
#pragma unroll
        for (int j = 0; j < 8; j++) {
            uint2 vh, vl; split4(rx[j], vh, vl);
            *(uint2*)(S + G2_XH + (xrow_lo + j * 16) * X2ROW + xc4 * 4) = vh;
            *(uint2*)(S + G2_XL + (xrow_lo + j * 16) * X2ROW + xc4 * 4) = vl;
        }
#pragma unroll
        for (int j = 0; j < 2; j++) {
            int row = arow_lo + j * 32;
            *(uint2*)(S + G2_AH + row * X2ROW + ac8 * 8)     = make_uint2(rah[j].x, rah[j].y);
            *(uint2*)(S + G2_AH + row * X2ROW + ac8 * 8 + 4) = make_uint2(rah[j].z, rah[j].w);
            *(uint2*)(S + G2_AL + row * X2ROW + ac8 * 8)     = make_uint2(ral[j].x, ral[j].y);
            *(uint2*)(S + G2_AL + row * X2ROW + ac8 * 8 + 4) = make_uint2(ral[j].z, ral[j].w);
        }
        __syncthreads();

        if (c + 1 < c1) loadc(c + 1);

#pragma unroll
        for (int s = 0; s < 4; s++) {
            uint32_t ah[4], al[4];
            ldmx4(ah, sbb + G2_XH * 2 + (uint32_t)(s * 16) * 2 + aoff);
            ldmx4(al, sbb + G2_XL * 2 + (uint32_t)(s * 16) * 2 + aoff);
#pragma unroll
            for (int np = 0; np < 4; np++) {
                uint32_t bh[4], bl[4];
                uint32_t bb = (uint32_t)(np * 16 * X2ROW + s * 16) * 2 + boff2;
                ldmx4(bh, sbb + G2_AH * 2 + bb);
                ldmx4(bl, sbb + G2_AL * 2 + bb);
                mma_bf16(cacc[2 * np],     ah, bh);     mma_bf16(cacc[2 * np],     ah, bl);
                mma_bf16(cacc[2 * np],     al, bh);
                mma_bf16(cacc[2 * np + 1], ah, bh + 2); mma_bf16(cacc[2 * np + 1], ah, bl + 2);
                mma_bf16(cacc[2 * np + 1], al, bh + 2);
            }
        }
    }

    const int da = d0 + wid * 16 + g;
    const int db = da + 8;
#pragma unroll
    for (int n = 0; n < 8; n++) {
#pragma unroll
        for (int i = 0; i < 2; i++) {
            const int k = n * 8 + 2 * t + i;
            atomicAdd(&g_vlad[((size_t)b * KK + k) * DD + da], cacc[n][i]);
            atomicAdd(&g_vlad[((size_t)b * KK + k) * DD + db], cacc[n][2 + i]);
        }
    }
}

// ================= K3: subtract a_sum*centroid, intra-norm, per-b sumsq =================
__global__ __launch_bounds__(128) void k_intranorm(const float* __restrict__ centroids) {
    __shared__ float sred[4];
    const int row = blockIdx.x;
    const int tid = threadIdx.x, lane = tid & 31, w = tid >> 5;
    const float as = g_asum[row];
    float4* v = (float4*)(g_vlad + (size_t)row * 512);
    float4 val = v[tid];
    const float4 cv = ((const float4*)(centroids + (size_t)(row & 63) * DD))[tid];
    val.x -= as * cv.x; val.y -= as * cv.y; val.z -= as * cv.z; val.w -= as * cv.w;
    float ss = val.x * val.x + val.y * val.y + val.z * val.z + val.w * val.w;
    ss += __shfl_xor_sync(0xffffffffu, ss, 16);
    ss += __shfl_xor_sync(0xffffffffu, ss, 8);
    ss += __shfl_xor_sync(0xffffffffu, ss, 4);
    ss += __shfl_xor_sync(0xffffffffu, ss, 2);
    ss += __shfl_xor_sync(0xffffffffu, ss, 1);
    if (lane == 0) sred[w] = ss;
    __syncthreads();
    float tot = sred[0] + sred[1] + sred[2] + sred[3];
    float scale = 1.f / fmaxf(sqrtf(tot), 1e-12f);
    val.x *= scale; val.y *= scale; val.z *= scale; val.w *= scale;
    v[tid] = val;
    if (tid == 0) atomicAdd(&g_bsq[row >> 6], tot * scale * scale);
}

// ================= K4: reduction GEMM on HMMA (register prefetch) =================
#define RROW 72
__global__ __launch_bounds__(256) void k_reduce(const float* __restrict__ red_w) {
    __shared__ uint16_t WH[64 * RROW], WL[64 * RROW];
    __shared__ uint16_t VH[32 * RROW], VL[32 * RROW];
    __shared__ float sBS[32];
    const int tid = threadIdx.x, wid = tid >> 5, lane = tid & 31;
    const int g = lane >> 2, t = lane & 3;
    const int o0 = blockIdx.x * 64;
    const int j0 = blockIdx.y * 2048;
    const int warp_m = (wid & 3) * 16;
    const int warp_n = (wid >> 2) * 16;

    if (tid < 32) sBS[tid] = 1.f / fmaxf(sqrtf(g_bsq[tid]), 1e-12f);
    __syncthreads();

    float cacc[2][4];
#pragma unroll
    for (int n = 0; n < 2; n++)
#pragma unroll
        for (int i = 0; i < 4; i++) cacc[n][i] = 0.f;

    const uint32_t whb = smem_u32(WH), wlb = smem_u32(WL);
    const uint32_t vhb = smem_u32(VH), vlb = smem_u32(VL);
    const uint32_t aoff = (uint32_t)((warp_m + (lane & 15)) * RROW + (lane >> 4) * 8) * 2;
    const uint32_t boff = (uint32_t)((warp_n + (lane & 7) + ((lane >> 4) & 1) * 8) * RROW +
                                     ((lane >> 3) & 1) * 8) * 2;

    const int wrow_lo = tid >> 4, wc4 = tid & 15;

    float4 rw[4], rv[2];
#pragma unroll
    for (int j = 0; j < 4; j++)
        rw[j] = *(const float4*)(red_w + (size_t)(o0 + wrow_lo + j * 16) * KD + j0 + wc4 * 4);
#pragma unroll
    for (int j = 0; j < 2; j++)
        rv[j] = *(const float4*)(g_vlad + (size_t)(wrow_lo + j * 16) * KD + j0 + wc4 * 4);

    for (int c = 0; c < 32; c++) {
        __syncthreads();
#pragma unroll
        for (int j = 0; j < 4; j++) {
            uint2 vh, vl; split4(rw[j], vh, vl);
            *(uint2*)(WH + (wrow_lo + j * 16) * RROW + wc4 * 4) = vh;
            *(uint2*)(WL + (wrow_lo + j * 16) * RROW + wc4 * 4) = vl;
        }
#pragma unroll
        for (int j = 0; j < 2; j++) {
            int row = wrow_lo + j * 16;
            float bs = sBS[row];
            float4 vv = rv[j];
            vv.x *= bs; vv.y *= bs; vv.z *= bs; vv.w *= bs;
            uint2 vh, vl; split4(vv, vh, vl);
            *(uint2*)(VH + row * RROW + wc4 * 4) = vh;
            *(uint2*)(VL + row * RROW + wc4 * 4) = vl;
        }
        __syncthreads();

        if (c + 1 < 32) {
            const int jc = j0 + (c + 1) * 64;
#pragma unroll
            for (int j = 0; j < 4; j++)
                rw[j] = *(const float4*)(red_w + (size_t)(o0 + wrow_lo + j * 16) * KD + jc + wc4 * 4);
#pragma unroll
            for (int j = 0; j < 2; j++)
                rv[j] = *(const float4*)(g_vlad + (size_t)(wrow_lo + j * 16) * KD + jc + wc4 * 4);
        }

#pragma unroll
        for (int ks = 0; ks < 4; ks++) {
            const uint32_t co = (uint32_t)(ks * 16) * 2;
            uint32_t ah[4], al[4], bh[4], bl[4];
            ldmx4(ah, whb + co + aoff);
            ldmx4(al, wlb + co + aoff);
            ldmx4(bh, vhb + co + boff);
            ldmx4(bl, vlb + co + boff);
            mma_bf16(cacc[0], ah, bh);     mma_bf16(cacc[0], ah, bl);
            mma_bf16(cacc[0], al, bh);
            mma_bf16(cacc[1], ah, bh + 2); mma_bf16(cacc[1], ah, bl + 2);
            mma_bf16(cacc[1], al, bh + 2);
        }
    }

#pragma unroll
    for (int nt = 0; nt < 2; nt++) {
        const int bcol = warp_n + nt * 8 + 2 * t;
        const int oa = o0 + warp_m + g;
        atomicAdd(&g_outpre[(size_t)bcol * OUTN + oa],           cacc[nt][0]);
        atomicAdd(&g_outpre[(size_t)(bcol + 1) * OUTN + oa],     cacc[nt][1]);
        atomicAdd(&g_outpre[(size_t)bcol * OUTN + oa + 8],       cacc[nt][2]);
        atomicAdd(&g_outpre[(size_t)(bcol + 1) * OUTN + oa + 8], cacc[nt][3]);
    }
}

// ================= K5: LayerNorm =================
__global__ __launch_bounds__(256) void k_ln(
    const float* __restrict__ gamma, const float* __restrict__ beta,
    float* __restrict__ out)
{
    __shared__ float sred[8];
    const int b = blockIdx.x, tid = threadIdx.x, lane = tid & 31, w = tid >> 5;
    float4 v = ((const float4*)(g_outpre + (size_t)b * OUTN))[tid];
    float s = v.x + v.y + v.z + v.w;
    s += __shfl_xor_sync(0xffffffffu, s, 16);
    s += __shfl_xor_sync(0xffffffffu, s, 8);
    s += __shfl_xor_sync(0xffffffffu, s, 4);
    s += __shfl_xor_sync(0xffffffffu, s, 2);
    s += __shfl_xor_sync(0xffffffffu, s, 1);
    if (lane == 0) sred[w] = s;
    __syncthreads();
    float tot = 0.f;
#pragma unroll
    for (int i = 0; i < 8; i++) tot += sred[i];
    const float mu = tot * (1.f / 1024.f);
    float dx0 = v.x - mu, dx1 = v.y - mu, dx2 = v.z - mu, dx3 = v.w - mu;
    float vs = dx0 * dx0 + dx1 * dx1 + dx2 * dx2 + dx3 * dx3;
    vs += __shfl_xor_sync(0xffffffffu, vs, 16);
    vs += __shfl_xor_sync(0xffffffffu, vs, 8);
    vs += __shfl_xor_sync(0xffffffffu, vs, 4);
    vs += __shfl_xor_sync(0xffffffffu, vs, 2);
    vs += __shfl_xor_sync(0xffffffffu, vs, 1);
    __syncthreads();
    if (lane == 0) sred[w] = vs;
    __syncthreads();
    float vtot = 0.f;
#pragma unroll
    for (int i = 0; i < 8; i++) vtot += sred[i];
    const float inv = 1.f / sqrtf(vtot * (1.f / 1024.f) + 1e-5f);
    float4 gm = ((const float4*)gamma)[tid];
    float4 be = ((const float4*)beta)[tid];
    float4 r;
    r.x = dx0 * inv * gm.x + be.x;
    r.y = dx1 * inv * gm.y + be.y;
    r.z = dx2 * inv * gm.z + be.z;
    r.w = dx3 * inv * gm.w + be.w;
    ((float4*)(out + (size_t)b * OUTN))[tid] = r;
}

// ================= launch =================
extern "C" void kernel_launch(void* const* d_in, const int* in_sizes, int n_in,
                              void* d_out, int out_size)
{
    const float* x         = (const float*)d_in[0];
    const int*   mask      = (const int*)d_in[1];
    const float* centroids = (const float*)d_in[2];
    const float* conv_w    = (const float*)d_in[3];
    const float* red_w     = (const float*)d_in[4];
    const float* gamma     = (const float*)d_in[5];
    const float* beta      = (const float*)d_in[6];
    float* out = (float*)d_out;

    cudaFuncSetAttribute(k_g1, cudaFuncAttributeMaxDynamicSharedMemorySize, G1_SMEM);
    cudaFuncSetAttribute(k_g2, cudaFuncAttributeMaxDynamicSharedMemorySize, G2_SMEM);

    k_zero<<<BB * KD / 256, 256>>>();
    k_wsplit<<<KK * DD / 256, 256>>>(conv_w);
    k_g1<<<dim3(BB, 25), 256, G1_SMEM>>>(x, mask);
    k_g2<<<dim3(BB, 4, 4), 256, G2_SMEM>>>(x);
    k_intranorm<<<BB * KK, 128>>>(centroids);
    k_reduce<<<dim3(16, 16), 256>>>(red_w);
    k_ln<<<BB, 256>>>(gamma, beta, out);
}

// round 14
// speedup vs baseline: 1.3112x; 1.0079x over previous
#include <cuda_runtime.h>
#include <cuda_bf16.h>
#include <math.h>
#include <cstdint>

#define BB 32
#define DD 512
#define TT 64
#define RR 49
#define TR 3136
#define KK 64
#define OUTN 1024
#define KD 32768

// ================= mma / ldmatrix =================
__device__ __forceinline__ void mma_bf16(float* c, const uint32_t* a, const uint32_t* b) {
    asm volatile(
        "mma.sync.aligned.m16n8k16.row.col.f32.bf16.bf16.f32 "
        "{%0,%1,%2,%3}, {%4,%5,%6,%7}, {%8,%9}, {%0,%1,%2,%3};"
        : "+f"(c[0]), "+f"(c[1]), "+f"(c[2]), "+f"(c[3])
        : "r"(a[0]), "r"(a[1]), "r"(a[2]), "r"(a[3]), "r"(b[0]), "r"(b[1]));
}
__device__ __forceinline__ void ldmx4(uint32_t* r, uint32_t a) {
    asm volatile("ldmatrix.sync.aligned.m8n8.x4.shared.b16 {%0,%1,%2,%3}, [%4];"
                 : "=r"(r[0]), "=r"(r[1]), "=r"(r[2]), "=r"(r[3]) : "r"(a));
}
__device__ __forceinline__ void ldmx4t(uint32_t* r, uint32_t a) {
    asm volatile("ldmatrix.sync.aligned.m8n8.x4.trans.shared.b16 {%0,%1,%2,%3}, [%4];"
                 : "=r"(r[0]), "=r"(r[1]), "=r"(r[2]), "=r"(r[3]) : "r"(a));
}
__device__ __forceinline__ uint32_t smem_u32(const void* p) {
    uint32_t a;
    asm("{ .reg .u64 t; cvta.to.shared.u64 t, %1; cvt.u32.u64 %0, t; }" : "=r"(a) : "l"(p));
    return a;
}
__device__ __forceinline__ void split_bf(float f, __nv_bfloat16& h, __nv_bfloat16& l) {
    h = __float2bfloat16(f);
    l = __float2bfloat16(f - __bfloat162float(h));
}
__device__ __forceinline__ uint32_t prmt(uint32_t a, uint32_t b, uint32_t sel) {
    uint32_t r; asm("prmt.b32 %0, %1, %2, %3;" : "=r"(r) : "r"(a), "r"(b), "r"(sel)); return r;
}
// Truncation split of 8 floats -> hi uint4, lo uint4 (STS.128-ready)
__device__ __forceinline__ void split8(float4 a, float4 b, uint4& vh, uint4& vl) {
    uint32_t u0 = __float_as_uint(a.x), u1 = __float_as_uint(a.y);
    uint32_t u2 = __float_as_uint(a.z), u3 = __float_as_uint(a.w);
    uint32_t u4 = __float_as_uint(b.x), u5 = __float_as_uint(b.y);
    uint32_t u6 = __float_as_uint(b.z), u7 = __float_as_uint(b.w);
    vh.x = prmt(u0, u1, 0x7632); vh.y = prmt(u2, u3, 0x7632);
    vh.z = prmt(u4, u5, 0x7632); vh.w = prmt(u6, u7, 0x7632);
    float l0 = a.x - __uint_as_float(u0 & 0xffff0000u);
    float l1 = a.y - __uint_as_float(u1 & 0xffff0000u);
    float l2 = a.z - __uint_as_float(u2 & 0xffff0000u);
    float l3 = a.w - __uint_as_float(u3 & 0xffff0000u);
    float l4 = b.x - __uint_as_float(u4 & 0xffff0000u);
    float l5 = b.y - __uint_as_float(u5 & 0xffff0000u);
    float l6 = b.z - __uint_as_float(u6 & 0xffff0000u);
    float l7 = b.w - __uint_as_float(u7 & 0xffff0000u);
    asm("cvt.rn.bf16x2.f32 %0, %1, %2;" : "=r"(vl.x) : "f"(l1), "f"(l0));
    asm("cvt.rn.bf16x2.f32 %0, %1, %2;" : "=r"(vl.y) : "f"(l3), "f"(l2));
    asm("cvt.rn.bf16x2.f32 %0, %1, %2;" : "=r"(vl.z) : "f"(l5), "f"(l4));
    asm("cvt.rn.bf16x2.f32 %0, %1, %2;" : "=r"(vl.w) : "f"(l7), "f"(l6));
}
__device__ __forceinline__ void split4(float4 v, uint2& vh, uint2& vl) {
    uint32_t ux = __float_as_uint(v.x), uy = __float_as_uint(v.y);
    uint32_t uz = __float_as_uint(v.z), uw = __float_as_uint(v.w);
    vh.x = prmt(ux, uy, 0x7632);
    vh.y = prmt(uz, uw, 0x7632);
    float lx = v.x - __uint_as_float(ux & 0xffff0000u);
    float ly = v.y - __uint_as_float(uy & 0xffff0000u);
    float lz = v.z - __uint_as_float(uz & 0xffff0000u);
    float lw = v.w - __uint_as_float(uw & 0xffff0000u);
    asm("cvt.rn.bf16x2.f32 %0, %1, %2;" : "=r"(vl.x) : "f"(ly), "f"(lx));
    asm("cvt.rn.bf16x2.f32 %0, %1, %2;" : "=r"(vl.y) : "f"(lw), "f"(lz));
}

// ================= scratch =================
__device__ __align__(256) __nv_bfloat16 g_ass_hi[(size_t)BB * KK * TR];
__device__ __align__(256) __nv_bfloat16 g_ass_lo[(size_t)BB * KK * TR];
__device__ __align__(256) __nv_bfloat16 g_w_hi[KK * DD];
__device__ __align__(256) __nv_bfloat16 g_w_lo[KK * DD];
__device__ __align__(256) float g_asum[BB * KK];
__device__ __align__(256) float g_vlad[BB * KD];
__device__ __align__(256) float g_bsq[BB];
__device__ __align__(256) float g_outpre[BB * OUTN];

__global__ void k_zero() {
    int i = blockIdx.x * 256 + threadIdx.x;
    g_vlad[i] = 0.f;
    if (i < BB * OUTN) g_outpre[i] = 0.f;
    if (i < BB * KK)   g_asum[i]   = 0.f;
    if (i < BB)        g_bsq[i]    = 0.f;
}

__global__ __launch_bounds__(256) void k_wsplit(const float* __restrict__ conv_w) {
    int i = blockIdx.x * 256 + threadIdx.x;
    if (i < KK * DD) {
        float f = conv_w[i];
        uint32_t u = __float_as_uint(f);
        float lo = f - __uint_as_float(u & 0xffff0000u);
        g_w_hi[i] = __ushort_as_bfloat16((unsigned short)(u >> 16));
        g_w_lo[i] = __float2bfloat16(lo);
    }
}

extern __shared__ unsigned char smx[];
#define SR 72   // smem row stride (bf16 elems) for all 64-col tiles

// ================= GEMM1: logits -> softmax -> assign + a_sum =================
// grid (32, 49), block 128 (4 warps). C tile [64 tr x 64 k]; K loop: d chunks of 64.
// 3136 = 49*64: no tails, no guards.
#define G1_XH 0
#define G1_XL (64 * SR)
#define G1_WH (2 * 64 * SR)
#define G1_WL (2 * 64 * SR + 64 * SR)
#define G1_END (4 * 64 * SR)
#define G1_SMEM (G1_END * 2 + 256)

__global__ __launch_bounds__(128) void k_g1(const float* __restrict__ x,
                                            const int* __restrict__ mask) {
    uint16_t* S = (uint16_t*)smx;
    float* sAs = (float*)(S + G1_END);
    const uint32_t sb = smem_u32(S);
    const int tid = threadIdx.x, wid = tid >> 5, lane = tid & 31;
    const int g = lane >> 2, t = lane & 3;
    const int b = blockIdx.x, tr0 = blockIdx.y * 64;

    if (tid < 64) sAs[tid] = 0.f;

    float cacc[8][4];
#pragma unroll
    for (int n = 0; n < 8; n++)
#pragma unroll
        for (int i = 0; i < 4; i++) cacc[n][i] = 0.f;

    const uint32_t aoff = (uint32_t)(((lane >> 4) * 8 + (lane & 7)) * SR +
                                     wid * 16 + ((lane >> 3) & 1) * 8) * 2;
    const uint32_t boff2 = (uint32_t)(((lane & 7) + ((lane >> 4) & 1) * 8) * SR +
                                      ((lane >> 3) & 1) * 8) * 2;

    // x staging: 64 d-rows x 64 tr; thread owns 8 consecutive tr (xc8) on 4 row-passes
    const int xrow_lo = tid >> 3, xc8 = tid & 7;      // rows: xrow_lo + j*16
    const int wrow_lo = tid >> 3, wc8 = tid & 7;      // W copy rows: + j*16

    float4 rx[8];
#pragma unroll
    for (int j = 0; j < 4; j++) {
        const float* p = x + ((size_t)b * DD + xrow_lo + j * 16) * TR + tr0 + xc8 * 8;
        rx[2 * j]     = *(const float4*)p;
        rx[2 * j + 1] = *(const float4*)(p + 4);
    }

    for (int q = 0; q < 8; q++) {
        __syncthreads();
#pragma unroll
        for (int j = 0; j < 4; j++) {
            uint4 vh, vl; split8(rx[2 * j], rx[2 * j + 1], vh, vl);
            *(uint4*)(S + G1_XH + (xrow_lo + j * 16) * SR + xc8 * 8) = vh;
            *(uint4*)(S + G1_XL + (xrow_lo + j * 16) * SR + xc8 * 8) = vl;
        }
#pragma unroll
        for (int j = 0; j < 4; j++) {   // W chunk copy (bf16, L2-hot)
            int row = wrow_lo + j * 16;
            size_t src = (size_t)row * DD + q * 64 + wc8 * 8;
            *(uint4*)(S + G1_WH + row * SR + wc8 * 8) = *(const uint4*)(g_w_hi + src);
            *(uint4*)(S + G1_WL + row * SR + wc8 * 8) = *(const uint4*)(g_w_lo + src);
        }
        __syncthreads();

        if (q < 7) {
#pragma unroll
            for (int j = 0; j < 4; j++) {
                const float* p = x + ((size_t)b * DD + (q + 1) * 64 + xrow_lo + j * 16) * TR + tr0 + xc8 * 8;
                rx[2 * j]     = *(const float4*)p;
                rx[2 * j + 1] = *(const float4*)(p + 4);
            }
        }

#pragma unroll
        for (int s = 0; s < 4; s++) {
            uint32_t ah[4], al[4];
            ldmx4t(ah, sb + G1_XH * 2 + (uint32_t)(s * 16 * SR) * 2 + aoff);
            ldmx4t(al, sb + G1_XL * 2 + (uint32_t)(s * 16 * SR) * 2 + aoff);
#pragma unroll
            for (int np = 0; np < 4; np++) {
                uint32_t bh[4], bl[4];
                uint32_t bb = (uint32_t)(np * 16 * SR + s * 16) * 2 + boff2;
                ldmx4(bh, sb + G1_WH * 2 + bb);
                ldmx4(bl, sb + G1_WL * 2 + bb);
                mma_bf16(cacc[2 * np],     ah, bh);     mma_bf16(cacc[2 * np],     ah, bl);
                mma_bf16(cacc[2 * np],     al, bh);
                mma_bf16(cacc[2 * np + 1], ah, bh + 2); mma_bf16(cacc[2 * np + 1], ah, bl + 2);
                mma_bf16(cacc[2 * np + 1], al, bh + 2);
            }
        }
    }

    const int tra = tr0 + wid * 16 + g;
    const int trb = tra + 8;
    float ma = -1e30f, mb = -1e30f;
#pragma unroll
    for (int n = 0; n < 8; n++) {
        ma = fmaxf(ma, fmaxf(cacc[n][0], cacc[n][1]));
        mb = fmaxf(mb, fmaxf(cacc[n][2], cacc[n][3]));
    }
    ma = fmaxf(ma, __shfl_xor_sync(0xffffffffu, ma, 1));
    ma = fmaxf(ma, __shfl_xor_sync(0xffffffffu, ma, 2));
    mb = fmaxf(mb, __shfl_xor_sync(0xffffffffu, mb, 1));
    mb = fmaxf(mb, __shfl_xor_sync(0xffffffffu, mb, 2));
    float sa = 0.f, sb2 = 0.f;
#pragma unroll
    for (int n = 0; n < 8; n++) {
        cacc[n][0] = __expf(cacc[n][0] - ma); sa += cacc[n][0];
        cacc[n][1] = __expf(cacc[n][1] - ma); sa += cacc[n][1];
        cacc[n][2] = __expf(cacc[n][2] - mb); sb2 += cacc[n][2];
        cacc[n][3] = __expf(cacc[n][3] - mb); sb2 += cacc[n][3];
    }
    sa  += __shfl_xor_sync(0xffffffffu, sa, 1);
    sa  += __shfl_xor_sync(0xffffffffu, sa, 2);
    sb2 += __shfl_xor_sync(0xffffffffu, sb2, 1);
    sb2 += __shfl_xor_sync(0xffffffffu, sb2, 2);
    const float inva = (float)mask[b * TT + tra / RR] / sa;
    const float invb = (float)mask[b * TT + trb / RR] / sb2;

#pragma unroll
    for (int n = 0; n < 8; n++) {
#pragma unroll
        for (int i = 0; i < 2; i++) {
            const int k = n * 8 + 2 * t + i;
            float aa = cacc[n][i] * inva;
            float ab = cacc[n][2 + i] * invb;
            {
                __nv_bfloat16 h, l; split_bf(aa, h, l);
                size_t o = ((size_t)b * KK + k) * TR + tra;
                g_ass_hi[o] = h; g_ass_lo[o] = l;
            }
            {
                __nv_bfloat16 h, l; split_bf(ab, h, l);
                size_t o = ((size_t)b * KK + k) * TR + trb;
                g_ass_hi[o] = h; g_ass_lo[o] = l;
            }
            float sum = aa + ab;
            sum += __shfl_xor_sync(0xffffffffu, sum, 4);
            sum += __shfl_xor_sync(0xffffffffu, sum, 8);
            sum += __shfl_xor_sync(0xffffffffu, sum, 16);
            if (g == 0) atomicAdd(&sAs[k], sum);
        }
    }
    __syncthreads();
    if (tid < 64) atomicAdd(&g_asum[b * 64 + tid], sAs[tid]);
}

// ================= GEMM2: vlad_partial[b,k,d] += sum_tr a*x =================
// grid (32, 8, 4), block 128 (4 warps). C tile [64 d x 64 k]; tr chunks split 4 ways.
#define G2_XH 0
#define G2_XL (64 * SR)
#define G2_AH (2 * 64 * SR)
#define G2_AL (2 * 64 * SR + 64 * SR)
#define G2_END (4 * 64 * SR)
#define G2_SMEM (G2_END * 2 + 256)

__global__ __launch_bounds__(128) void k_g2(const float* __restrict__ x) {
    uint16_t* S = (uint16_t*)smx;
    const uint32_t sbb = smem_u32(S);
    const int tid = threadIdx.x, wid = tid >> 5, lane = tid & 31;
    const int g = lane >> 2, t = lane & 3;
    const int b = blockIdx.x, d0 = blockIdx.y * 64, sp = blockIdx.z;
    const int c0 = sp ? 12 * sp + 1 : 0;
    const int c1 = (sp == 3) ? 49 : 12 * (sp + 1) + 1;

    float cacc[8][4];
#pragma unroll
    for (int n = 0; n < 8; n++)
#pragma unroll
        for (int i = 0; i < 4; i++) cacc[n][i] = 0.f;

    const uint32_t aoff = (uint32_t)((wid * 16 + (lane & 15)) * SR + (lane >> 4) * 8) * 2;
    const uint32_t boff2 = (uint32_t)(((lane & 7) + ((lane >> 4) & 1) * 8) * SR +
                                      ((lane >> 3) & 1) * 8) * 2;

    const int xrow_lo = tid >> 3, xc8 = tid & 7;   // x rows: + j*16
    const int arow_lo = tid >> 3, ac8 = tid & 7;   // assign rows: + j*16

    float4 rx[8];
    auto loadx = [&](int c) {
        const int trn = c * 64;
#pragma unroll
        for (int j = 0; j < 4; j++) {
            const float* p = x + ((size_t)b * DD + d0 + xrow_lo + j * 16) * TR + trn + xc8 * 8;
            rx[2 * j]     = *(const float4*)p;
            rx[2 * j + 1] = *(const float4*)(p + 4);
        }
    };

    loadx(c0);

    for (int c = c0; c < c1; c++) {
        const int trc = c * 64;
        __syncthreads();
#pragma unroll
        for (int j = 0; j < 4; j++) {
            uint4 vh, vl; split8(rx[2 * j], rx[2 * j + 1], vh, vl);
            *(uint4*)(S + G2_XH + (xrow_lo + j * 16) * SR + xc8 * 8) = vh;
            *(uint4*)(S + G2_XL + (xrow_lo + j * 16) * SR + xc8 * 8) = vl;
        }
#pragma unroll
        for (int j = 0; j < 4; j++) {   // assign copy (bf16, L2-hot)
            int row = arow_lo + j * 16;
            size_t src = ((size_t)b * KK + row) * TR + trc + ac8 * 8;
            *(uint4*)(S + G2_AH + row * SR + ac8 * 8) = *(const uint4*)(g_ass_hi + src);
            *(uint4*)(S + G2_AL + row * SR + ac8 * 8) = *(const uint4*)(g_ass_lo + src);
        }
        __syncthreads();

        if (c + 1 < c1) loadx(c + 1);

#pragma unroll
        for (int s = 0; s < 4; s++) {
            uint32_t ah[4], al[4];
            ldmx4(ah, sbb + G2_XH * 2 + (uint32_t)(s * 16) * 2 + aoff);
            ldmx4(al, sbb + G2_XL * 2 + (uint32_t)(s * 16) * 2 + aoff);
#pragma unroll
            for (int np = 0; np < 4; np++) {
                uint32_t bh[4], bl[4];
                uint32_t bb = (uint32_t)(np * 16 * SR + s * 16) * 2 + boff2;
                ldmx4(bh, sbb + G2_AH * 2 + bb);
                ldmx4(bl, sbb + G2_AL * 2 + bb);
                mma_bf16(cacc[2 * np],     ah, bh);     mma_bf16(cacc[2 * np],     ah, bl);
                mma_bf16(cacc[2 * np],     al, bh);
                mma_bf16(cacc[2 * np + 1], ah, bh + 2); mma_bf16(cacc[2 * np + 1], ah, bl + 2);
                mma_bf16(cacc[2 * np + 1], al, bh + 2);
            }
        }
    }

    const int da = d0 + wid * 16 + g;
    const int db = da + 8;
#pragma unroll
    for (int n = 0; n < 8; n++) {
#pragma unroll
        for (int i = 0; i < 2; i++) {
            const int k = n * 8 + 2 * t + i;
            atomicAdd(&g_vlad[((size_t)b * KK + k) * DD + da], cacc[n][i]);
            atomicAdd(&g_vlad[((size_t)b * KK + k) * DD + db], cacc[n][2 + i]);
        }
    }
}

// ================= K3: subtract a_sum*centroid, intra-norm, per-b sumsq =================
__global__ __launch_bounds__(128) void k_intranorm(const float* __restrict__ centroids) {
    __shared__ float sred[4];
    const int row = blockIdx.x;
    const int tid = threadIdx.x, lane = tid & 31, w = tid >> 5;
    const float as = g_asum[row];
    float4* v = (float4*)(g_vlad + (size_t)row * 512);
    float4 val = v[tid];
    const float4 cv = ((const float4*)(centroids + (size_t)(row & 63) * DD))[tid];
    val.x -= as * cv.x; val.y -= as * cv.y; val.z -= as * cv.z; val.w -= as * cv.w;
    float ss = val.x * val.x + val.y * val.y + val.z * val.z + val.w * val.w;
    ss += __shfl_xor_sync(0xffffffffu, ss, 16);
    ss += __shfl_xor_sync(0xffffffffu, ss, 8);
    ss += __shfl_xor_sync(0xffffffffu, ss, 4);
    ss += __shfl_xor_sync(0xffffffffu, ss, 2);
    ss += __shfl_xor_sync(0xffffffffu, ss, 1);
    if (lane == 0) sred[w] = ss;
    __syncthreads();
    float tot = sred[0] + sred[1] + sred[2] + sred[3];
    float scale = 1.f / fmaxf(sqrtf(tot), 1e-12f);
    val.x *= scale; val.y *= scale; val.z *= scale; val.w *= scale;
    v[tid] = val;
    if (tid == 0) atomicAdd(&g_bsq[row >> 6], tot * scale * scale);
}

// ================= K4: reduction GEMM on HMMA (register prefetch) =================
#define RROW 72
__global__ __launch_bounds__(256) void k_reduce(const float* __restrict__ red_w) {
    __shared__ uint16_t WH[64 * RROW], WL[64 * RROW];
    __shared__ uint16_t VH[32 * RROW], VL[32 * RROW];
    __shared__ float sBS[32];
    const int tid = threadIdx.x, wid = tid >> 5, lane = tid & 31;
    const int g = lane >> 2, t = lane & 3;
    const int o0 = blockIdx.x * 64;
    const int j0 = blockIdx.y * 2048;
    const int warp_m = (wid & 3) * 16;
    const int warp_n = (wid >> 2) * 16;

    if (tid < 32) sBS[tid] = 1.f / fmaxf(sqrtf(g_bsq[tid]), 1e-12f);
    __syncthreads();

    float cacc[2][4];
#pragma unroll
    for (int n = 0; n < 2; n++)
#pragma unroll
        for (int i = 0; i < 4; i++) cacc[n][i] = 0.f;

    const uint32_t whb = smem_u32(WH), wlb = smem_u32(WL);
    const uint32_t vhb = smem_u32(VH), vlb = smem_u32(VL);
    const uint32_t aoff = (uint32_t)((warp_m + (lane & 15)) * RROW + (lane >> 4) * 8) * 2;
    const uint32_t boff = (uint32_t)((warp_n + (lane & 7) + ((lane >> 4) & 1) * 8) * RROW +
                                     ((lane >> 3) & 1) * 8) * 2;

    const int wrow_lo = tid >> 4, wc4 = tid & 15;

    float4 rw[4], rv[2];
#pragma unroll
    for (int j = 0; j < 4; j++)
        rw[j] = *(const float4*)(red_w + (size_t)(o0 + wrow_lo + j * 16) * KD + j0 + wc4 * 4);
#pragma unroll
    for (int j = 0; j < 2; j++)
        rv[j] = *(const float4*)(g_vlad + (size_t)(wrow_lo + j * 16) * KD + j0 + wc4 * 4);

    for (int c = 0; c < 32; c++) {
        __syncthreads();
#pragma unroll
        for (int j = 0; j < 4; j++) {
            uint2 vh, vl; split4(rw[j], vh, vl);
            *(uint2*)(WH + (wrow_lo + j * 16) * RROW + wc4 * 4) = vh;
            *(uint2*)(WL + (wrow_lo + j * 16) * RROW + wc4 * 4) = vl;
        }
#pragma unroll
        for (int j = 0; j < 2; j++) {
            int row = wrow_lo + j * 16;
            float bs = sBS[row];
            float4 vv = rv[j];
            vv.x *= bs; vv.y *= bs; vv.z *= bs; vv.w *= bs;
            uint2 vh, vl; split4(vv, vh, vl);
            *(uint2*)(VH + row * RROW + wc4 * 4) = vh;
            *(uint2*)(VL + row * RROW + wc4 * 4) = vl;
        }
        __syncthreads();

        if (c + 1 < 32) {
            const int jc = j0 + (c + 1) * 64;
#pragma unroll
            for (int j = 0; j < 4; j++)
                rw[j] = *(const float4*)(red_w + (size_t)(o0 + wrow_lo + j * 16) * KD + jc + wc4 * 4);
#pragma unroll
            for (int j = 0; j < 2; j++)
                rv[j] = *(const float4*)(g_vlad + (size_t)(wrow_lo + j * 16) * KD + jc + wc4 * 4);
        }

#pragma unroll
        for (int ks = 0; ks < 4; ks++) {
            const uint32_t co = (uint32_t)(ks * 16) * 2;
            uint32_t ah[4], al[4], bh[4], bl[4];
            ldmx4(ah, whb + co + aoff);
            ldmx4(al, wlb + co + aoff);
            ldmx4(bh, vhb + co + boff);
            ldmx4(bl, vlb + co + boff);
            mma_bf16(cacc[0], ah, bh);     mma_bf16(cacc[0], ah, bl);
            mma_bf16(cacc[0], al, bh);
            mma_bf16(cacc[1], ah, bh + 2); mma_bf16(cacc[1], ah, bl + 2);
            mma_bf16(cacc[1], al, bh + 2);
        }
    }

#pragma unroll
    for (int nt = 0; nt < 2; nt++) {
        const int bcol = warp_n + nt * 8 + 2 * t;
        const int oa = o0 + warp_m + g;
        atomicAdd(&g_outpre[(size_t)bcol * OUTN + oa],           cacc[nt][0]);
        atomicAdd(&g_outpre[(size_t)(bcol + 1) * OUTN + oa],     cacc[nt][1]);
        atomicAdd(&g_outpre[(size_t)bcol * OUTN + oa + 8],       cacc[nt][2]);
        atomicAdd(&g_outpre[(size_t)(bcol + 1) * OUTN + oa + 8], cacc[nt][3]);
    }
}

// ================= K5: LayerNorm =================
__global__ __launch_bounds__(256) void k_ln(
    const float* __restrict__ gamma, const float* __restrict__ beta,
    float* __restrict__ out)
{
    __shared__ float sred[8];
    const int b = blockIdx.x, tid = threadIdx.x, lane = tid & 31, w = tid >> 5;
    float4 v = ((const float4*)(g_outpre + (size_t)b * OUTN))[tid];
    float s = v.x + v.y + v.z + v.w;
    s += __shfl_xor_sync(0xffffffffu, s, 16);
    s += __shfl_xor_sync(0xffffffffu, s, 8);
    s += __shfl_xor_sync(0xffffffffu, s, 4);
    s += __shfl_xor_sync(0xffffffffu, s, 2);
    s += __shfl_xor_sync(0xffffffffu, s, 1);
    if (lane == 0) sred[w] = s;
    __syncthreads();
    float tot = 0.f;
#pragma unroll
    for (int i = 0; i < 8; i++) tot += sred[i];
    const float mu = tot * (1.f / 1024.f);
    float dx0 = v.x - mu, dx1 = v.y - mu, dx2 = v.z - mu, dx3 = v.w - mu;
    float vs = dx0 * dx0 + dx1 * dx1 + dx2 * dx2 + dx3 * dx3;
    vs += __shfl_xor_sync(0xffffffffu, vs, 16);
    vs += __shfl_xor_sync(0xffffffffu, vs, 8);
    vs += __shfl_xor_sync(0xffffffffu, vs, 4);
    vs += __shfl_xor_sync(0xffffffffu, vs, 2);
    vs += __shfl_xor_sync(0xffffffffu, vs, 1);
    __syncthreads();
    if (lane == 0) sred[w] = vs;
    __syncthreads();
    float vtot = 0.f;
#pragma unroll
    for (int i = 0; i < 8; i++) vtot += sred[i];
    const float inv = 1.f / sqrtf(vtot * (1.f / 1024.f) + 1e-5f);
    float4 gm = ((const float4*)gamma)[tid];
    float4 be = ((const float4*)beta)[tid];
    float4 r;
    r.x = dx0 * inv * gm.x + be.x;
    r.y = dx1 * inv * gm.y + be.y;
    r.z = dx2 * inv * gm.z + be.z;
    r.w = dx3 * inv * gm.w + be.w;
    ((float4*)(out + (size_t)b * OUTN))[tid] = r;
}

// ================= launch =================
extern "C" void kernel_launch(void* const* d_in, const int* in_sizes, int n_in,
                              void* d_out, int out_size)
{
    const float* x         = (const float*)d_in[0];
    const int*   mask      = (const int*)d_in[1];
    const float* centroids = (const float*)d_in[2];
    const float* conv_w    = (const float*)d_in[3];
    const float* red_w     = (const float*)d_in[4];
    const float* gamma     = (const float*)d_in[5];
    const float* beta      = (const float*)d_in[6];
    float* out = (float*)d_out;

    cudaFuncSetAttribute(k_g1, cudaFuncAttributeMaxDynamicSharedMemorySize, G1_SMEM);
    cudaFuncSetAttribute(k_g2, cudaFuncAttributeMaxDynamicSharedMemorySize, G2_SMEM);

    k_zero<<<BB * KD / 256, 256>>>();
    k_wsplit<<<KK * DD / 256, 256>>>(conv_w);
    k_g1<<<dim3(BB, 49), 128, G1_SMEM>>>(x, mask);
    k_g2<<<dim3(BB, 8, 4), 128, G2_SMEM>>>(x);
    k_intranorm<<<BB * KK, 128>>>(centroids);
    k_reduce<<<dim3(16, 16), 256>>>(red_w);
    k_ln<<<BB, 256>>>(gamma, beta, out);
}